// round 1
// baseline (speedup 1.0000x reference)
#include <cuda_runtime.h>
#include <cuda_bf16.h>
#include <math.h>

// Problem constants
#define BV 32
#define TT 256
#define EE 384
#define HH 6
#define DD 64
#define LL 6
#define FF 1536
#define VVOC 32000
#define MM (BV*TT)   // 8192 rows

// ---------------- scratch (static device buffers; no allocation) ----------------
__device__ float g_x [MM*EE];
__device__ float g_h [MM*EE];
__device__ float g_q [MM*EE];
__device__ float g_k [MM*EE];
__device__ float g_v [MM*EE];
__device__ float g_ao[MM*EE];
__device__ float g_ff[MM*FF];

// ---------------- embedding: x = tok_emb[idx] + pos_emb ----------------
__global__ void embed_kernel(const int* __restrict__ idx, const float* __restrict__ tok,
                             const float* __restrict__ pos, float* __restrict__ x)
{
    int i = blockIdx.x * blockDim.x + threadIdx.x;
    if (i >= MM*EE) return;
    int e   = i % EE;
    int row = i / EE;
    int t   = row % TT;
    x[i] = tok[(size_t)idx[row]*EE + e] + pos[t*EE + e];
}

// ---------------- layernorm: out = (x-mean)*rsqrt(var+eps)*s + b ----------------
__global__ void ln_kernel(const float* __restrict__ in, float* __restrict__ out,
                          const float* __restrict__ s, const float* __restrict__ b)
{
    int row = blockIdx.x;
    const float* xr = in + (size_t)row*EE;
    float ls = 0.f, lq = 0.f;
    for (int e = threadIdx.x; e < EE; e += 128) {
        float v = xr[e];
        ls += v;
        lq += v*v;
    }
    #pragma unroll
    for (int o = 16; o > 0; o >>= 1) {
        ls += __shfl_down_sync(0xffffffffu, ls, o);
        lq += __shfl_down_sync(0xffffffffu, lq, o);
    }
    __shared__ float ss[4], sq[4];
    int w = threadIdx.x >> 5, lane = threadIdx.x & 31;
    if (lane == 0) { ss[w] = ls; sq[w] = lq; }
    __syncthreads();
    float tot  = ss[0] + ss[1] + ss[2] + ss[3];
    float totq = sq[0] + sq[1] + sq[2] + sq[3];
    float mean = tot * (1.0f/EE);
    float var  = totq * (1.0f/EE) - mean*mean;
    float inv  = rsqrtf(var + 1e-5f);
    for (int e = threadIdx.x; e < EE; e += 128)
        out[(size_t)row*EE + e] = (xr[e] - mean) * inv * s[e] + b[e];
}

// ---------------- SGEMM: C [=|+=] relu?(A@B + bias) ----------------
// A: [M,K] row-major, B: [K,N] row-major. 128x128 tile, BK=8, 8x8 per thread.
// Requires M%128==0, N%128==0, K%8==0 (all shapes here satisfy this).
template<int RELU, int ACC>
__global__ void __launch_bounds__(256)
sgemm_kernel(const float* __restrict__ A, const float* __restrict__ B,
             const float* __restrict__ bias, float* __restrict__ C,
             int M, int N, int K)
{
    __shared__ float As[8][128];
    __shared__ float Bs[8][128];

    int tid = threadIdx.x;
    int tx = tid & 15;         // 0..15 (col group)
    int ty = tid >> 4;         // 0..15 (row group)
    int row0 = blockIdx.y * 128;
    int col0 = blockIdx.x * 128;

    // A loader: 128 rows x 8 cols; thread -> (row = tid/2, col4 = (tid&1)*4)
    int ar = tid >> 1;
    int ac = (tid & 1) * 4;
    const float* Aptr = A + (size_t)(row0 + ar) * K + ac;
    // B loader: 8 rows x 128 cols; thread -> (row = tid/32, col4 = (tid&31)*4)
    int br = tid >> 5;
    int bc = (tid & 31) * 4;
    const float* Bptr = B + (size_t)br * N + col0 + bc;

    float acc[8][8];
    #pragma unroll
    for (int i = 0; i < 8; i++)
        #pragma unroll
        for (int j = 0; j < 8; j++) acc[i][j] = 0.f;

    for (int k0 = 0; k0 < K; k0 += 8) {
        float4 av = *(const float4*)(Aptr + k0);
        As[ac+0][ar] = av.x;
        As[ac+1][ar] = av.y;
        As[ac+2][ar] = av.z;
        As[ac+3][ar] = av.w;
        float4 bv = *(const float4*)(Bptr + (size_t)k0 * N);
        *(float4*)&Bs[br][bc] = bv;
        __syncthreads();

        #pragma unroll
        for (int k = 0; k < 8; k++) {
            float a[8], bb[8];
            *(float4*)&a[0]  = *(const float4*)&As[k][ty*8];
            *(float4*)&a[4]  = *(const float4*)&As[k][ty*8+4];
            *(float4*)&bb[0] = *(const float4*)&Bs[k][tx*8];
            *(float4*)&bb[4] = *(const float4*)&Bs[k][tx*8+4];
            #pragma unroll
            for (int i = 0; i < 8; i++)
                #pragma unroll
                for (int j = 0; j < 8; j++)
                    acc[i][j] = fmaf(a[i], bb[j], acc[i][j]);
        }
        __syncthreads();
    }

    // epilogue
    #pragma unroll
    for (int i = 0; i < 8; i++) {
        size_t r = (size_t)(row0 + ty*8 + i);
        #pragma unroll
        for (int j = 0; j < 8; j += 4) {
            int c = col0 + tx*8 + j;
            float4 val = make_float4(acc[i][j], acc[i][j+1], acc[i][j+2], acc[i][j+3]);
            if (bias) {
                float4 bv = *(const float4*)(bias + c);
                val.x += bv.x; val.y += bv.y; val.z += bv.z; val.w += bv.w;
            }
            if (RELU) {
                val.x = fmaxf(val.x, 0.f); val.y = fmaxf(val.y, 0.f);
                val.z = fmaxf(val.z, 0.f); val.w = fmaxf(val.w, 0.f);
            }
            float* cp = C + r * N + c;
            if (ACC) {
                float4 old = *(const float4*)cp;
                val.x += old.x; val.y += old.y; val.z += old.z; val.w += old.w;
            }
            *(float4*)cp = val;
        }
    }
}

// ---------------- fused causal attention, one (b,h) per block ----------------
// K,V tiles (256x64 fp32 each = 128KB) in dynamic SMEM; one thread per query row,
// online softmax entirely in registers.
__global__ void __launch_bounds__(256)
attn_kernel(const float* __restrict__ q, const float* __restrict__ k,
            const float* __restrict__ v, float* __restrict__ o)
{
    extern __shared__ float4 sm4[];
    float4* K4 = sm4;            // TT*16 float4
    float4* V4 = sm4 + TT*16;

    int b = blockIdx.x / HH;
    int h = blockIdx.x % HH;
    int tid = threadIdx.x;

    const float4* kg = (const float4*)(k + (size_t)b*TT*EE + h*DD);
    const float4* vg = (const float4*)(v + (size_t)b*TT*EE + h*DD);
    // row j, chunk d4 -> global float4 index j*(EE/4) + d4 = j*96 + d4
    for (int idx = tid; idx < TT*16; idx += 256) {
        int j  = idx >> 4;
        int d4 = idx & 15;
        K4[idx] = kg[j*96 + d4];
        V4[idx] = vg[j*96 + d4];
    }
    __syncthreads();

    int i = tid;  // query index
    const float4* qg = (const float4*)(q + (size_t)(b*TT + i)*EE + h*DD);
    float4 qv[16];
    #pragma unroll
    for (int d4 = 0; d4 < 16; d4++) qv[d4] = qg[d4];

    float4 ov[16];
    #pragma unroll
    for (int d4 = 0; d4 < 16; d4++) ov[d4] = make_float4(0.f, 0.f, 0.f, 0.f);

    float m = -1e30f, lsum = 0.f;
    const float scale = 0.125f;  // D^-0.5

    for (int j = 0; j <= i; j++) {
        float4 s4 = make_float4(0.f, 0.f, 0.f, 0.f);
        #pragma unroll
        for (int d4 = 0; d4 < 16; d4++) {
            float4 kk = K4[j*16 + d4];
            s4.x = fmaf(qv[d4].x, kk.x, s4.x);
            s4.y = fmaf(qv[d4].y, kk.y, s4.y);
            s4.z = fmaf(qv[d4].z, kk.z, s4.z);
            s4.w = fmaf(qv[d4].w, kk.w, s4.w);
        }
        float s = ((s4.x + s4.y) + (s4.z + s4.w)) * scale;
        float mn = fmaxf(m, s);
        float c = __expf(m - mn);
        float p = __expf(s - mn);
        lsum = lsum * c + p;
        #pragma unroll
        for (int d4 = 0; d4 < 16; d4++) {
            float4 vv = V4[j*16 + d4];
            ov[d4].x = fmaf(ov[d4].x, c, p*vv.x);
            ov[d4].y = fmaf(ov[d4].y, c, p*vv.y);
            ov[d4].z = fmaf(ov[d4].z, c, p*vv.z);
            ov[d4].w = fmaf(ov[d4].w, c, p*vv.w);
        }
        m = mn;
    }

    float r = 1.0f / lsum;
    float4* og = (float4*)(o + (size_t)(b*TT + i)*EE + h*DD);
    #pragma unroll
    for (int d4 = 0; d4 < 16; d4++)
        og[d4] = make_float4(ov[d4].x*r, ov[d4].y*r, ov[d4].z*r, ov[d4].w*r);
}

// ---------------- launcher ----------------
extern "C" void kernel_launch(void* const* d_in, const int* in_sizes, int n_in,
                              void* d_out, int out_size)
{
    (void)in_sizes; (void)n_in; (void)out_size;
    const int*   idx  = (const int*)  d_in[0];
    const float* tok  = (const float*)d_in[1];
    const float* pos  = (const float*)d_in[2];
    const float* Wq   = (const float*)d_in[3];
    const float* Wk   = (const float*)d_in[4];
    const float* Wv   = (const float*)d_in[5];
    const float* Wo   = (const float*)d_in[6];
    const float* bo   = (const float*)d_in[7];
    const float* ln1s = (const float*)d_in[8];
    const float* ln1b = (const float*)d_in[9];
    const float* ln2s = (const float*)d_in[10];
    const float* ln2b = (const float*)d_in[11];
    const float* W1   = (const float*)d_in[12];
    const float* b1   = (const float*)d_in[13];
    const float* W2   = (const float*)d_in[14];
    const float* b2   = (const float*)d_in[15];
    const float* lnfs = (const float*)d_in[16];
    const float* lnfb = (const float*)d_in[17];
    const float* Wh   = (const float*)d_in[18];
    const float* bh   = (const float*)d_in[19];
    float* out = (float*)d_out;

    float *x, *h, *q, *k, *v, *ao, *ff;
    cudaGetSymbolAddress((void**)&x,  g_x);
    cudaGetSymbolAddress((void**)&h,  g_h);
    cudaGetSymbolAddress((void**)&q,  g_q);
    cudaGetSymbolAddress((void**)&k,  g_k);
    cudaGetSymbolAddress((void**)&v,  g_v);
    cudaGetSymbolAddress((void**)&ao, g_ao);
    cudaGetSymbolAddress((void**)&ff, g_ff);

    cudaFuncSetAttribute(attn_kernel, cudaFuncAttributeMaxDynamicSharedMemorySize, 131072);

    dim3 blk(256);
    embed_kernel<<<(MM*EE + 255)/256, 256>>>(idx, tok, pos, x);

    dim3 gE(EE/128, MM/128);   // N=384
    dim3 gF(FF/128, MM/128);   // N=1536
    dim3 gV(VVOC/128, MM/128); // N=32000

    for (int l = 0; l < LL; l++) {
        ln_kernel<<<MM, 128>>>(x, h, ln1s + l*EE, ln1b + l*EE);
        sgemm_kernel<0,0><<<gE, blk>>>(h, Wq + (size_t)l*EE*EE, nullptr, q, MM, EE, EE);
        sgemm_kernel<0,0><<<gE, blk>>>(h, Wk + (size_t)l*EE*EE, nullptr, k, MM, EE, EE);
        sgemm_kernel<0,0><<<gE, blk>>>(h, Wv + (size_t)l*EE*EE, nullptr, v, MM, EE, EE);
        attn_kernel<<<BV*HH, 256, 131072>>>(q, k, v, ao);
        sgemm_kernel<0,1><<<gE, blk>>>(ao, Wo + (size_t)l*EE*EE, bo + l*EE, x, MM, EE, EE);
        ln_kernel<<<MM, 128>>>(x, h, ln2s + l*EE, ln2b + l*EE);
        sgemm_kernel<1,0><<<gF, blk>>>(h, W1 + (size_t)l*EE*FF, b1 + l*FF, ff, MM, FF, EE);
        sgemm_kernel<0,1><<<gE, blk>>>(ff, W2 + (size_t)l*FF*EE, b2 + l*EE, x, MM, EE, FF);
    }
    ln_kernel<<<MM, 128>>>(x, h, lnfs, lnfb);
    sgemm_kernel<0,0><<<gV, blk>>>(h, Wh, bh, out, MM, VVOC, EE);
}

// round 2
// speedup vs baseline: 1.9608x; 1.9608x over previous
#include <cuda_runtime.h>
#include <cuda_bf16.h>
#include <math.h>
#include <stdint.h>

// Problem constants
#define BV 32
#define TT 256
#define EE 384
#define HH 6
#define DD 64
#define LL 6
#define FF 1536
#define VVOC 32000
#define MM (BV*TT)   // 8192 rows

// ---------------- scratch (static device buffers; no allocation) ----------------
__device__ float g_x [MM*EE];
__device__ float g_h [MM*EE];
__device__ float g_q [MM*EE];
__device__ float g_k [MM*EE];
__device__ float g_v [MM*EE];
__device__ float g_ao[MM*EE];
__device__ float g_ff[MM*FF];

// ---------------- embedding ----------------
__global__ void embed_kernel(const int* __restrict__ idx, const float* __restrict__ tok,
                             const float* __restrict__ pos, float* __restrict__ x)
{
    int i = blockIdx.x * blockDim.x + threadIdx.x;
    if (i >= MM*EE) return;
    int e   = i % EE;
    int row = i / EE;
    int t   = row % TT;
    x[i] = tok[(size_t)idx[row]*EE + e] + pos[t*EE + e];
}

// ---------------- layernorm ----------------
__global__ void ln_kernel(const float* __restrict__ in, float* __restrict__ out,
                          const float* __restrict__ s, const float* __restrict__ b)
{
    int row = blockIdx.x;
    const float* xr = in + (size_t)row*EE;
    float ls = 0.f, lq = 0.f;
    for (int e = threadIdx.x; e < EE; e += 128) {
        float v = xr[e];
        ls += v;
        lq += v*v;
    }
    #pragma unroll
    for (int o = 16; o > 0; o >>= 1) {
        ls += __shfl_down_sync(0xffffffffu, ls, o);
        lq += __shfl_down_sync(0xffffffffu, lq, o);
    }
    __shared__ float ss[4], sq[4];
    int w = threadIdx.x >> 5, lane = threadIdx.x & 31;
    if (lane == 0) { ss[w] = ls; sq[w] = lq; }
    __syncthreads();
    float tot  = ss[0] + ss[1] + ss[2] + ss[3];
    float totq = sq[0] + sq[1] + sq[2] + sq[3];
    float mean = tot * (1.0f/EE);
    float var  = totq * (1.0f/EE) - mean*mean;
    float inv  = rsqrtf(var + 1e-5f);
    for (int e = threadIdx.x; e < EE; e += 128)
        out[(size_t)row*EE + e] = (xr[e] - mean) * inv * s[e] + b[e];
}

// ---------------- tf32 helpers ----------------
__device__ __forceinline__ uint32_t f2tf32(float f) {
    uint32_t r;
    asm("cvt.rna.tf32.f32 %0, %1;" : "=r"(r) : "f"(f));
    return r;
}

__device__ __forceinline__ void mma_tf32(float* c, const uint32_t* a, const uint32_t* b) {
    asm volatile(
        "mma.sync.aligned.m16n8k8.row.col.f32.tf32.tf32.f32 "
        "{%0,%1,%2,%3}, {%4,%5,%6,%7}, {%8,%9}, {%0,%1,%2,%3};"
        : "+f"(c[0]), "+f"(c[1]), "+f"(c[2]), "+f"(c[3])
        : "r"(a[0]), "r"(a[1]), "r"(a[2]), "r"(a[3]), "r"(b[0]), "r"(b[1]));
}

// ---------------- tf32 tensor-core GEMM ----------------
// C[M,N] [=|+=] relu?(A[M,K] @ B[K,N] + bias)
// Block tile 128x128, BK=32, 256 threads = 8 warps (4m x 2n), warp tile 32x64.
// Requires M%128==0, N%128==0, K%32==0 (all shapes satisfy).
template<int RELU, int ACC>
__global__ void __launch_bounds__(256)
tgemm_kernel(const float* __restrict__ A, const float* __restrict__ B,
             const float* __restrict__ bias, float* __restrict__ C,
             int M, int N, int K)
{
    // As[m][k]: stride 36 (pad) -> conflict-free fragment loads
    // Bs[k][n]: stride 128, column swizzled by n ^ (8*(k&3))
    __shared__ uint32_t As[128*36];
    __shared__ uint32_t Bs[32*128];

    const int tid  = threadIdx.x;
    const int lane = tid & 31;
    const int wid  = tid >> 5;
    const int wm   = wid & 3;    // 0..3
    const int wn   = wid >> 2;   // 0..1
    const int g    = lane >> 2;  // 0..7
    const int t    = lane & 3;   // 0..3

    const int row0 = blockIdx.y * 128;
    const int col0 = blockIdx.x * 128;

    // global loaders
    const int am = tid >> 1;              // 0..127
    const int ak = (tid & 1) * 16;        // 0 or 16
    const int bk = tid >> 5;              // 0..7
    const int bn = (tid & 31) * 4;        // 0..124

    const float* Ag = A + (size_t)(row0 + am) * K + ak;
    const float* Bg = B + (size_t)bk * N + col0 + bn;

    float4 pa[4], pb[4];
    #pragma unroll
    for (int i = 0; i < 4; i++) pa[i] = *(const float4*)(Ag + i*4);
    #pragma unroll
    for (int p = 0; p < 4; p++) pb[p] = *(const float4*)(Bg + (size_t)p*8*N);

    float acc[2][8][4];
    #pragma unroll
    for (int mi = 0; mi < 2; mi++)
        #pragma unroll
        for (int ni = 0; ni < 8; ni++)
            #pragma unroll
            for (int r = 0; r < 4; r++) acc[mi][ni][r] = 0.f;

    const int KT = K >> 5;
    for (int kt = 0; kt < KT; kt++) {
        // commit prefetched tiles to smem (converted to tf32)
        #pragma unroll
        for (int i = 0; i < 4; i++) {
            uint32_t* dst = &As[am*36 + ak + i*4];
            dst[0] = f2tf32(pa[i].x); dst[1] = f2tf32(pa[i].y);
            dst[2] = f2tf32(pa[i].z); dst[3] = f2tf32(pa[i].w);
        }
        #pragma unroll
        for (int p = 0; p < 4; p++) {
            int kk = bk + p*8;
            uint32_t* dst = &Bs[kk*128 + (bn ^ (8*(kk & 3)))];
            dst[0] = f2tf32(pb[p].x); dst[1] = f2tf32(pb[p].y);
            dst[2] = f2tf32(pb[p].z); dst[3] = f2tf32(pb[p].w);
        }
        __syncthreads();

        if (kt + 1 < KT) {
            Ag += 32;
            Bg += (size_t)32 * N;
            #pragma unroll
            for (int i = 0; i < 4; i++) pa[i] = *(const float4*)(Ag + i*4);
            #pragma unroll
            for (int p = 0; p < 4; p++) pb[p] = *(const float4*)(Bg + (size_t)p*8*N);
        }

        #pragma unroll
        for (int ks = 0; ks < 4; ks++) {
            const int k0 = ks * 8;
            uint32_t af[2][4], bf[8][2];
            #pragma unroll
            for (int mi = 0; mi < 2; mi++) {
                int m = wm*32 + mi*16 + g;
                af[mi][0] = As[m*36 + k0 + t];
                af[mi][1] = As[(m+8)*36 + k0 + t];
                af[mi][2] = As[m*36 + k0 + t + 4];
                af[mi][3] = As[(m+8)*36 + k0 + t + 4];
            }
            const int kk = k0 + t;
            const int sw = 8 * t;   // (kk & 3) == t since k0 % 8 == 0
            #pragma unroll
            for (int ni = 0; ni < 8; ni++) {
                int n = wn*64 + ni*8 + g;
                bf[ni][0] = Bs[kk*128 + (n ^ sw)];
                bf[ni][1] = Bs[(kk+4)*128 + (n ^ sw)];
            }
            #pragma unroll
            for (int mi = 0; mi < 2; mi++)
                #pragma unroll
                for (int ni = 0; ni < 8; ni++)
                    mma_tf32(acc[mi][ni], af[mi], bf[ni]);
        }
        __syncthreads();
    }

    // epilogue
    #pragma unroll
    for (int mi = 0; mi < 2; mi++) {
        #pragma unroll
        for (int ni = 0; ni < 8; ni++) {
            int row = row0 + wm*32 + mi*16 + g;
            int col = col0 + wn*64 + ni*8 + t*2;
            float v0 = acc[mi][ni][0], v1 = acc[mi][ni][1];
            float v2 = acc[mi][ni][2], v3 = acc[mi][ni][3];
            if (bias) {
                float b0 = bias[col], b1 = bias[col+1];
                v0 += b0; v1 += b1; v2 += b0; v3 += b1;
            }
            if (RELU) {
                v0 = fmaxf(v0, 0.f); v1 = fmaxf(v1, 0.f);
                v2 = fmaxf(v2, 0.f); v3 = fmaxf(v3, 0.f);
            }
            float* c0 = C + (size_t)row * N + col;
            float* c1 = C + (size_t)(row + 8) * N + col;
            if (ACC) {
                float2 o0 = *(const float2*)c0;
                float2 o1 = *(const float2*)c1;
                v0 += o0.x; v1 += o0.y; v2 += o1.x; v3 += o1.y;
            }
            *(float2*)c0 = make_float2(v0, v1);
            *(float2*)c1 = make_float2(v2, v3);
        }
    }
}

// ---------------- fused causal attention ----------------
__global__ void __launch_bounds__(256)
attn_kernel(const float* __restrict__ q, const float* __restrict__ k,
            const float* __restrict__ v, float* __restrict__ o)
{
    extern __shared__ float4 sm4[];
    float4* K4 = sm4;
    float4* V4 = sm4 + TT*16;

    int b = blockIdx.x / HH;
    int h = blockIdx.x % HH;
    int tid = threadIdx.x;

    const float4* kg = (const float4*)(k + (size_t)b*TT*EE + h*DD);
    const float4* vg = (const float4*)(v + (size_t)b*TT*EE + h*DD);
    for (int idx = tid; idx < TT*16; idx += 256) {
        int j  = idx >> 4;
        int d4 = idx & 15;
        K4[idx] = kg[j*96 + d4];
        V4[idx] = vg[j*96 + d4];
    }
    __syncthreads();

    int i = tid;
    const float4* qg = (const float4*)(q + (size_t)(b*TT + i)*EE + h*DD);
    float4 qv[16];
    #pragma unroll
    for (int d4 = 0; d4 < 16; d4++) qv[d4] = qg[d4];

    float4 ov[16];
    #pragma unroll
    for (int d4 = 0; d4 < 16; d4++) ov[d4] = make_float4(0.f, 0.f, 0.f, 0.f);

    float m = -1e30f, lsum = 0.f;
    const float scale = 0.125f;

    for (int j = 0; j <= i; j++) {
        float4 s4 = make_float4(0.f, 0.f, 0.f, 0.f);
        #pragma unroll
        for (int d4 = 0; d4 < 16; d4++) {
            float4 kk = K4[j*16 + d4];
            s4.x = fmaf(qv[d4].x, kk.x, s4.x);
            s4.y = fmaf(qv[d4].y, kk.y, s4.y);
            s4.z = fmaf(qv[d4].z, kk.z, s4.z);
            s4.w = fmaf(qv[d4].w, kk.w, s4.w);
        }
        float s = ((s4.x + s4.y) + (s4.z + s4.w)) * scale;
        float mn = fmaxf(m, s);
        float c = __expf(m - mn);
        float p = __expf(s - mn);
        lsum = lsum * c + p;
        #pragma unroll
        for (int d4 = 0; d4 < 16; d4++) {
            float4 vv = V4[j*16 + d4];
            ov[d4].x = fmaf(ov[d4].x, c, p*vv.x);
            ov[d4].y = fmaf(ov[d4].y, c, p*vv.y);
            ov[d4].z = fmaf(ov[d4].z, c, p*vv.z);
            ov[d4].w = fmaf(ov[d4].w, c, p*vv.w);
        }
        m = mn;
    }

    float r = 1.0f / lsum;
    float4* og = (float4*)(o + (size_t)(b*TT + i)*EE + h*DD);
    #pragma unroll
    for (int d4 = 0; d4 < 16; d4++)
        og[d4] = make_float4(ov[d4].x*r, ov[d4].y*r, ov[d4].z*r, ov[d4].w*r);
}

// ---------------- launcher ----------------
extern "C" void kernel_launch(void* const* d_in, const int* in_sizes, int n_in,
                              void* d_out, int out_size)
{
    (void)in_sizes; (void)n_in; (void)out_size;
    const int*   idx  = (const int*)  d_in[0];
    const float* tok  = (const float*)d_in[1];
    const float* pos  = (const float*)d_in[2];
    const float* Wq   = (const float*)d_in[3];
    const float* Wk   = (const float*)d_in[4];
    const float* Wv   = (const float*)d_in[5];
    const float* Wo   = (const float*)d_in[6];
    const float* bo   = (const float*)d_in[7];
    const float* ln1s = (const float*)d_in[8];
    const float* ln1b = (const float*)d_in[9];
    const float* ln2s = (const float*)d_in[10];
    const float* ln2b = (const float*)d_in[11];
    const float* W1   = (const float*)d_in[12];
    const float* b1   = (const float*)d_in[13];
    const float* W2   = (const float*)d_in[14];
    const float* b2   = (const float*)d_in[15];
    const float* lnfs = (const float*)d_in[16];
    const float* lnfb = (const float*)d_in[17];
    const float* Wh   = (const float*)d_in[18];
    const float* bh   = (const float*)d_in[19];
    float* out = (float*)d_out;

    float *x, *h, *q, *k, *v, *ao, *ff;
    cudaGetSymbolAddress((void**)&x,  g_x);
    cudaGetSymbolAddress((void**)&h,  g_h);
    cudaGetSymbolAddress((void**)&q,  g_q);
    cudaGetSymbolAddress((void**)&k,  g_k);
    cudaGetSymbolAddress((void**)&v,  g_v);
    cudaGetSymbolAddress((void**)&ao, g_ao);
    cudaGetSymbolAddress((void**)&ff, g_ff);

    cudaFuncSetAttribute(attn_kernel, cudaFuncAttributeMaxDynamicSharedMemorySize, 131072);

    dim3 blk(256);
    embed_kernel<<<(MM*EE + 255)/256, 256>>>(idx, tok, pos, x);

    dim3 gE(EE/128, MM/128);   // N=384
    dim3 gF(FF/128, MM/128);   // N=1536
    dim3 gV(VVOC/128, MM/128); // N=32000

    for (int l = 0; l < LL; l++) {
        ln_kernel<<<MM, 128>>>(x, h, ln1s + l*EE, ln1b + l*EE);
        tgemm_kernel<0,0><<<gE, blk>>>(h, Wq + (size_t)l*EE*EE, nullptr, q, MM, EE, EE);
        tgemm_kernel<0,0><<<gE, blk>>>(h, Wk + (size_t)l*EE*EE, nullptr, k, MM, EE, EE);
        tgemm_kernel<0,0><<<gE, blk>>>(h, Wv + (size_t)l*EE*EE, nullptr, v, MM, EE, EE);
        attn_kernel<<<BV*HH, 256, 131072>>>(q, k, v, ao);
        tgemm_kernel<0,1><<<gE, blk>>>(ao, Wo + (size_t)l*EE*EE, bo + l*EE, x, MM, EE, EE);
        ln_kernel<<<MM, 128>>>(x, h, ln2s + l*EE, ln2b + l*EE);
        tgemm_kernel<1,0><<<gF, blk>>>(h, W1 + (size_t)l*EE*FF, b1 + l*FF, ff, MM, FF, EE);
        tgemm_kernel<0,1><<<gE, blk>>>(ff, W2 + (size_t)l*FF*EE, b2 + l*EE, x, MM, EE, FF);
    }
    ln_kernel<<<MM, 128>>>(x, h, lnfs, lnfb);
    tgemm_kernel<0,0><<<gV, blk>>>(h, Wh, bh, out, MM, VVOC, EE);
}

// round 3
// speedup vs baseline: 2.1102x; 1.0762x over previous
#include <cuda_runtime.h>
#include <cuda_bf16.h>
#include <math.h>
#include <stdint.h>

// Problem constants
#define BV 32
#define TT 256
#define EE 384
#define HH 6
#define DD 64
#define LL 6
#define FF 1536
#define VVOC 32000
#define MM (BV*TT)   // 8192 rows
#define E3 (3*EE)    // 1152

// ---------------- scratch (static device buffers; no allocation) ----------------
__device__ float g_x   [MM*EE];
__device__ float g_h   [MM*EE];
__device__ float g_qkv [MM*E3];
__device__ float g_ao  [MM*EE];
__device__ float g_ff  [MM*FF];
__device__ float g_wqkv[LL*EE*E3];

// ---------------- embedding ----------------
__global__ void embed_kernel(const int* __restrict__ idx, const float* __restrict__ tok,
                             const float* __restrict__ pos, float* __restrict__ x)
{
    int i = blockIdx.x * blockDim.x + threadIdx.x;
    if (i >= MM*EE) return;
    int e   = i % EE;
    int row = i / EE;
    int t   = row % TT;
    x[i] = tok[(size_t)idx[row]*EE + e] + pos[t*EE + e];
}

// ---------------- pack Wq|Wk|Wv -> [L][E][3E] ----------------
__global__ void pack_qkv_kernel(const float* __restrict__ Wq, const float* __restrict__ Wk,
                                const float* __restrict__ Wv, float* __restrict__ out)
{
    int i = blockIdx.x * blockDim.x + threadIdx.x;
    if (i >= LL*EE*E3) return;
    int c  = i % E3;
    int re = (i / E3);         // l*EE + e
    int sel = c / EE;
    int cc  = c % EE;
    const float* src = (sel == 0) ? Wq : (sel == 1) ? Wk : Wv;
    out[i] = src[(size_t)re*EE + cc];
}

// ---------------- layernorm ----------------
__global__ void ln_kernel(const float* __restrict__ in, float* __restrict__ out,
                          const float* __restrict__ s, const float* __restrict__ b)
{
    int row = blockIdx.x;
    const float* xr = in + (size_t)row*EE;
    float ls = 0.f, lq = 0.f;
    for (int e = threadIdx.x; e < EE; e += 128) {
        float v = xr[e];
        ls += v;
        lq += v*v;
    }
    #pragma unroll
    for (int o = 16; o > 0; o >>= 1) {
        ls += __shfl_down_sync(0xffffffffu, ls, o);
        lq += __shfl_down_sync(0xffffffffu, lq, o);
    }
    __shared__ float ss[4], sq[4];
    int w = threadIdx.x >> 5, lane = threadIdx.x & 31;
    if (lane == 0) { ss[w] = ls; sq[w] = lq; }
    __syncthreads();
    float tot  = ss[0] + ss[1] + ss[2] + ss[3];
    float totq = sq[0] + sq[1] + sq[2] + sq[3];
    float mean = tot * (1.0f/EE);
    float var  = totq * (1.0f/EE) - mean*mean;
    float inv  = rsqrtf(var + 1e-5f);
    for (int e = threadIdx.x; e < EE; e += 128)
        out[(size_t)row*EE + e] = (xr[e] - mean) * inv * s[e] + b[e];
}

// ---------------- tf32 helpers ----------------
__device__ __forceinline__ uint32_t f2tf32(float f) {
    uint32_t r;
    asm("cvt.rna.tf32.f32 %0, %1;" : "=r"(r) : "f"(f));
    return r;
}

__device__ __forceinline__ void mma_tf32(float* c, const uint32_t* a, const uint32_t* b) {
    asm volatile(
        "mma.sync.aligned.m16n8k8.row.col.f32.tf32.tf32.f32 "
        "{%0,%1,%2,%3}, {%4,%5,%6,%7}, {%8,%9}, {%0,%1,%2,%3};"
        : "+f"(c[0]), "+f"(c[1]), "+f"(c[2]), "+f"(c[3])
        : "r"(a[0]), "r"(a[1]), "r"(a[2]), "r"(a[3]), "r"(b[0]), "r"(b[1]));
}

__device__ __forceinline__ void cp_async16(uint32_t dst, const void* src) {
    asm volatile("cp.async.cg.shared.global [%0], [%1], 16;" :: "r"(dst), "l"(src));
}
__device__ __forceinline__ void cp_commit() {
    asm volatile("cp.async.commit_group;");
}
template<int N>
__device__ __forceinline__ void cp_wait() {
    asm volatile("cp.async.wait_group %0;" :: "n"(N));
}

// ---------------- tf32 tensor-core GEMM, cp.async 3-stage pipeline ----------------
// C[M,N] [=|+=] relu?(A[M,K] @ B[K,N] + bias)
// Block 128x128, BK=32, 256 threads = 8 warps (4m x 2n), warp tile 32x64.
// Requires M%128==0, N%128==0, K%32==0.
#define NSTAGE 3
#define A_FLOATS (128*36)
#define B_FLOATS (32*128)
#define STAGE_FLOATS (A_FLOATS + B_FLOATS)
#define GEMM_SMEM (NSTAGE*STAGE_FLOATS*4)

template<int RELU, int ACC>
__global__ void __launch_bounds__(256)
tgemm_kernel(const float* __restrict__ A, const float* __restrict__ B,
             const float* __restrict__ bias, float* __restrict__ C,
             int M, int N, int K)
{
    extern __shared__ float smem_f[];
    const uint32_t smem_u = (uint32_t)__cvta_generic_to_shared(smem_f);

    const int tid  = threadIdx.x;
    const int lane = tid & 31;
    const int wid  = tid >> 5;
    const int wm   = wid & 3;
    const int wn   = wid >> 2;
    const int g    = lane >> 2;
    const int t    = lane & 3;

    const int row0 = blockIdx.y * 128;
    const int col0 = blockIdx.x * 128;

    const int KT = K >> 5;

    // loader chunk decomposition (4 chunks of 16B each for A and B)
    int am[4], ak[4], bk[4], bn[4];
    #pragma unroll
    for (int i = 0; i < 4; i++) {
        int c = tid + 256*i;
        am[i] = c >> 3;  ak[i] = (c & 7) * 4;
        bk[i] = c >> 5;  bn[i] = (c & 31) * 4;
    }

    // issue one pipeline stage
    auto issue = [&](int kt) {
        int s = kt % NSTAGE;
        uint32_t a_st = smem_u + (uint32_t)(s * STAGE_FLOATS) * 4u;
        uint32_t b_st = a_st + A_FLOATS * 4u;
        #pragma unroll
        for (int i = 0; i < 4; i++)
            cp_async16(a_st + (uint32_t)(am[i]*36 + ak[i])*4u,
                       A + (size_t)(row0 + am[i]) * K + kt*32 + ak[i]);
        #pragma unroll
        for (int i = 0; i < 4; i++)
            cp_async16(b_st + (uint32_t)(bk[i]*128 + (bn[i] ^ (8*(bk[i]&3))))*4u,
                       B + (size_t)(kt*32 + bk[i]) * N + col0 + bn[i]);
        cp_commit();
    };

    float acc[2][8][4];
    #pragma unroll
    for (int mi = 0; mi < 2; mi++)
        #pragma unroll
        for (int ni = 0; ni < 8; ni++)
            #pragma unroll
            for (int r = 0; r < 4; r++) acc[mi][ni][r] = 0.f;

    // prologue: stages 0..NSTAGE-2
    issue(0);
    issue(1);

    for (int kt = 0; kt < KT; kt++) {
        cp_wait<NSTAGE-2>();
        __syncthreads();
        if (kt + NSTAGE - 1 < KT) issue(kt + NSTAGE - 1);

        const float* a_st = smem_f + (kt % NSTAGE) * STAGE_FLOATS;
        const float* b_st = a_st + A_FLOATS;

        #pragma unroll
        for (int ks = 0; ks < 4; ks++) {
            const int k0 = ks * 8;
            uint32_t af[2][4], bf[8][2];
            #pragma unroll
            for (int mi = 0; mi < 2; mi++) {
                int m = wm*32 + mi*16 + g;
                af[mi][0] = f2tf32(a_st[m*36 + k0 + t]);
                af[mi][1] = f2tf32(a_st[(m+8)*36 + k0 + t]);
                af[mi][2] = f2tf32(a_st[m*36 + k0 + t + 4]);
                af[mi][3] = f2tf32(a_st[(m+8)*36 + k0 + t + 4]);
            }
            const int kk = k0 + t;
            const int sw = 8 * t;
            #pragma unroll
            for (int ni = 0; ni < 8; ni++) {
                int n = wn*64 + ni*8 + g;
                bf[ni][0] = f2tf32(b_st[kk*128 + (n ^ sw)]);
                bf[ni][1] = f2tf32(b_st[(kk+4)*128 + (n ^ sw)]);
            }
            #pragma unroll
            for (int mi = 0; mi < 2; mi++)
                #pragma unroll
                for (int ni = 0; ni < 8; ni++)
                    mma_tf32(acc[mi][ni], af[mi], bf[ni]);
        }
        __syncthreads();
    }

    // epilogue
    #pragma unroll
    for (int mi = 0; mi < 2; mi++) {
        #pragma unroll
        for (int ni = 0; ni < 8; ni++) {
            int row = row0 + wm*32 + mi*16 + g;
            int col = col0 + wn*64 + ni*8 + t*2;
            float v0 = acc[mi][ni][0], v1 = acc[mi][ni][1];
            float v2 = acc[mi][ni][2], v3 = acc[mi][ni][3];
            if (bias) {
                float b0 = bias[col], b1 = bias[col+1];
                v0 += b0; v1 += b1; v2 += b0; v3 += b1;
            }
            if (RELU) {
                v0 = fmaxf(v0, 0.f); v1 = fmaxf(v1, 0.f);
                v2 = fmaxf(v2, 0.f); v3 = fmaxf(v3, 0.f);
            }
            float* c0 = C + (size_t)row * N + col;
            float* c1 = C + (size_t)(row + 8) * N + col;
            if (ACC) {
                float2 o0 = *(const float2*)c0;
                float2 o1 = *(const float2*)c1;
                v0 += o0.x; v1 += o0.y; v2 += o1.x; v3 += o1.y;
            }
            *(float2*)c0 = make_float2(v0, v1);
            *(float2*)c1 = make_float2(v2, v3);
        }
    }
}

// ---------------- fused causal attention ----------------
// One block per (b,h), 512 threads: 2 threads per query (even/odd j), shfl merge.
// Reads fused qkv buffer [MM][1152]; writes o [MM][384].
__global__ void __launch_bounds__(512)
attn_kernel(const float* __restrict__ qkv, float* __restrict__ o)
{
    extern __shared__ float4 sm4[];
    float4* K4 = sm4;
    float4* V4 = sm4 + TT*16;

    int b = blockIdx.x / HH;
    int h = blockIdx.x % HH;
    int tid = threadIdx.x;

    const float* base = qkv + (size_t)b*TT*E3;
    for (int idx = tid; idx < TT*16; idx += 512) {
        int j  = idx >> 4;
        int d4 = idx & 15;
        K4[idx] = ((const float4*)(base + (size_t)j*E3 + EE   + h*DD))[d4];
        V4[idx] = ((const float4*)(base + (size_t)j*E3 + 2*EE + h*DD))[d4];
    }
    __syncthreads();

    int i = tid >> 1;       // query index
    int p = tid & 1;        // j parity
    const float4* qg = (const float4*)(base + (size_t)i*E3 + h*DD);
    float4 qv[16];
    #pragma unroll
    for (int d4 = 0; d4 < 16; d4++) qv[d4] = qg[d4];

    float4 ov[16];
    #pragma unroll
    for (int d4 = 0; d4 < 16; d4++) ov[d4] = make_float4(0.f, 0.f, 0.f, 0.f);

    float m = -1e30f, lsum = 0.f;
    const float scale = 0.125f;

    for (int j = p; j <= i; j += 2) {
        float4 s4 = make_float4(0.f, 0.f, 0.f, 0.f);
        #pragma unroll
        for (int d4 = 0; d4 < 16; d4++) {
            float4 kk = K4[j*16 + d4];
            s4.x = fmaf(qv[d4].x, kk.x, s4.x);
            s4.y = fmaf(qv[d4].y, kk.y, s4.y);
            s4.z = fmaf(qv[d4].z, kk.z, s4.z);
            s4.w = fmaf(qv[d4].w, kk.w, s4.w);
        }
        float s = ((s4.x + s4.y) + (s4.z + s4.w)) * scale;
        float mn = fmaxf(m, s);
        float c = __expf(m - mn);
        float pw = __expf(s - mn);
        lsum = lsum * c + pw;
        #pragma unroll
        for (int d4 = 0; d4 < 16; d4++) {
            float4 vv = V4[j*16 + d4];
            ov[d4].x = fmaf(ov[d4].x, c, pw*vv.x);
            ov[d4].y = fmaf(ov[d4].y, c, pw*vv.y);
            ov[d4].z = fmaf(ov[d4].z, c, pw*vv.z);
            ov[d4].w = fmaf(ov[d4].w, c, pw*vv.w);
        }
        m = mn;
    }

    // merge the two partial softmaxes (lanes 2i, 2i+1)
    float mo = __shfl_xor_sync(0xffffffffu, m, 1);
    float lo = __shfl_xor_sync(0xffffffffu, lsum, 1);
    float mn = fmaxf(m, mo);
    float cs = __expf(m - mn);
    float co = __expf(mo - mn);
    float lm = lsum * cs + lo * co;
    float r = 1.0f / lm;

    float4* og = (float4*)(o + (size_t)(b*TT + i)*EE + h*DD);
    #pragma unroll
    for (int d4 = 0; d4 < 16; d4++) {
        float ox = ov[d4].x*cs + __shfl_xor_sync(0xffffffffu, ov[d4].x, 1)*co;
        float oy = ov[d4].y*cs + __shfl_xor_sync(0xffffffffu, ov[d4].y, 1)*co;
        float oz = ov[d4].z*cs + __shfl_xor_sync(0xffffffffu, ov[d4].z, 1)*co;
        float ow = ov[d4].w*cs + __shfl_xor_sync(0xffffffffu, ov[d4].w, 1)*co;
        if (p == 0)
            og[d4] = make_float4(ox*r, oy*r, oz*r, ow*r);
    }
}

// ---------------- launcher ----------------
extern "C" void kernel_launch(void* const* d_in, const int* in_sizes, int n_in,
                              void* d_out, int out_size)
{
    (void)in_sizes; (void)n_in; (void)out_size;
    const int*   idx  = (const int*)  d_in[0];
    const float* tok  = (const float*)d_in[1];
    const float* pos  = (const float*)d_in[2];
    const float* Wq   = (const float*)d_in[3];
    const float* Wk   = (const float*)d_in[4];
    const float* Wv   = (const float*)d_in[5];
    const float* Wo   = (const float*)d_in[6];
    const float* bo   = (const float*)d_in[7];
    const float* ln1s = (const float*)d_in[8];
    const float* ln1b = (const float*)d_in[9];
    const float* ln2s = (const float*)d_in[10];
    const float* ln2b = (const float*)d_in[11];
    const float* W1   = (const float*)d_in[12];
    const float* b1   = (const float*)d_in[13];
    const float* W2   = (const float*)d_in[14];
    const float* b2   = (const float*)d_in[15];
    const float* lnfs = (const float*)d_in[16];
    const float* lnfb = (const float*)d_in[17];
    const float* Wh   = (const float*)d_in[18];
    const float* bh   = (const float*)d_in[19];
    float* out = (float*)d_out;

    float *x, *h, *qkv, *ao, *ff, *wqkv;
    cudaGetSymbolAddress((void**)&x,    g_x);
    cudaGetSymbolAddress((void**)&h,    g_h);
    cudaGetSymbolAddress((void**)&qkv,  g_qkv);
    cudaGetSymbolAddress((void**)&ao,   g_ao);
    cudaGetSymbolAddress((void**)&ff,   g_ff);
    cudaGetSymbolAddress((void**)&wqkv, g_wqkv);

    cudaFuncSetAttribute(tgemm_kernel<0,0>, cudaFuncAttributeMaxDynamicSharedMemorySize, GEMM_SMEM);
    cudaFuncSetAttribute(tgemm_kernel<0,1>, cudaFuncAttributeMaxDynamicSharedMemorySize, GEMM_SMEM);
    cudaFuncSetAttribute(tgemm_kernel<1,0>, cudaFuncAttributeMaxDynamicSharedMemorySize, GEMM_SMEM);
    cudaFuncSetAttribute(attn_kernel, cudaFuncAttributeMaxDynamicSharedMemorySize, 131072);

    dim3 blk(256);
    embed_kernel<<<(MM*EE + 255)/256, 256>>>(idx, tok, pos, x);
    pack_qkv_kernel<<<(LL*EE*E3 + 255)/256, 256>>>(Wq, Wk, Wv, wqkv);

    dim3 gQKV(E3/128, MM/128);  // 9 x 64
    dim3 gE(EE/128, MM/128);    // 3 x 64
    dim3 gF(FF/128, MM/128);    // 12 x 64
    dim3 gV(VVOC/128, MM/128);  // 250 x 64

    for (int l = 0; l < LL; l++) {
        ln_kernel<<<MM, 128>>>(x, h, ln1s + l*EE, ln1b + l*EE);
        tgemm_kernel<0,0><<<gQKV, blk, GEMM_SMEM>>>(h, wqkv + (size_t)l*EE*E3, nullptr, qkv, MM, E3, EE);
        attn_kernel<<<BV*HH, 512, 131072>>>(qkv, ao);
        tgemm_kernel<0,1><<<gE, blk, GEMM_SMEM>>>(ao, Wo + (size_t)l*EE*EE, bo + l*EE, x, MM, EE, EE);
        ln_kernel<<<MM, 128>>>(x, h, ln2s + l*EE, ln2b + l*EE);
        tgemm_kernel<1,0><<<gF, blk, GEMM_SMEM>>>(h, W1 + (size_t)l*EE*FF, b1 + l*FF, ff, MM, FF, EE);
        tgemm_kernel<0,1><<<gE, blk, GEMM_SMEM>>>(ff, W2 + (size_t)l*FF*EE, b2 + l*EE, x, MM, EE, FF);
    }
    ln_kernel<<<MM, 128>>>(x, h, lnfs, lnfb);
    tgemm_kernel<0,0><<<gV, blk, GEMM_SMEM>>>(h, Wh, bh, out, MM, VVOC, EE);
}

// round 5
// speedup vs baseline: 2.4956x; 1.1826x over previous
#include <cuda_runtime.h>
#include <cuda_bf16.h>
#include <math.h>
#include <stdint.h>

// Problem constants
#define BV 32
#define TT 256
#define EE 384
#define HH 6
#define DD 64
#define LL 6
#define FF 1536
#define VVOC 32000
#define MM (BV*TT)   // 8192 rows
#define E3 (3*EE)    // 1152

// ---------------- scratch (static device buffers; no allocation) ----------------
__device__ float g_x   [MM*EE];
__device__ float g_h   [MM*EE];
__device__ float g_qkv [MM*E3];
__device__ float g_ao  [MM*EE];
__device__ float g_ff  [MM*FF];
__device__ float g_wqkv[LL*EE*E3];
__device__ float g_wo  [LL*EE*EE];
__device__ float g_w1  [LL*EE*FF];
__device__ float g_w2  [LL*FF*EE];
__device__ float g_wh  [EE*VVOC];

// ---------------- tf32 helpers ----------------
__device__ __forceinline__ float tf32r(float f) {
    uint32_t u;
    asm("cvt.rna.tf32.f32 %0, %1;" : "=r"(u) : "f"(f));
    return __uint_as_float(u);
}

__device__ __forceinline__ void mma_tf32(float* c, const uint32_t* a, const uint32_t* b) {
    asm volatile(
        "mma.sync.aligned.m16n8k8.row.col.f32.tf32.tf32.f32 "
        "{%0,%1,%2,%3}, {%4,%5,%6,%7}, {%8,%9}, {%0,%1,%2,%3};"
        : "+f"(c[0]), "+f"(c[1]), "+f"(c[2]), "+f"(c[3])
        : "r"(a[0]), "r"(a[1]), "r"(a[2]), "r"(a[3]), "r"(b[0]), "r"(b[1]));
}

__device__ __forceinline__ void cp_async16(uint32_t dst, const void* src) {
    asm volatile("cp.async.cg.shared.global [%0], [%1], 16;" :: "r"(dst), "l"(src));
}
__device__ __forceinline__ void cp_commit() {
    asm volatile("cp.async.commit_group;");
}
template<int N>
__device__ __forceinline__ void cp_wait() {
    asm volatile("cp.async.wait_group %0;" :: "n"(N));
}

// ---------------- embedding ----------------
__global__ void embed_kernel(const int* __restrict__ idx, const float* __restrict__ tok,
                             const float* __restrict__ pos, float* __restrict__ x)
{
    int i = blockIdx.x * blockDim.x + threadIdx.x;
    if (i >= MM*EE) return;
    int e   = i % EE;
    int row = i / EE;
    int t   = row % TT;
    x[i] = tok[(size_t)idx[row]*EE + e] + pos[t*EE + e];
}

// ---------------- weight prep: tf32-round copy ----------------
__global__ void round_copy_kernel(const float* __restrict__ src, float* __restrict__ dst, int n)
{
    int i = blockIdx.x * blockDim.x + threadIdx.x;
    if (i < n) dst[i] = tf32r(src[i]);
}

// pack Wq|Wk|Wv -> [L][E][3E], tf32-rounded
__global__ void pack_qkv_kernel(const float* __restrict__ Wq, const float* __restrict__ Wk,
                                const float* __restrict__ Wv, float* __restrict__ out)
{
    int i = blockIdx.x * blockDim.x + threadIdx.x;
    if (i >= LL*EE*E3) return;
    int c  = i % E3;
    int re = (i / E3);
    int sel = c / EE;
    int cc  = c % EE;
    const float* src = (sel == 0) ? Wq : (sel == 1) ? Wk : Wv;
    out[i] = tf32r(src[(size_t)re*EE + cc]);
}

// ---------------- layernorm (outputs tf32-rounded) ----------------
__global__ void ln_kernel(const float* __restrict__ in, float* __restrict__ out,
                          const float* __restrict__ s, const float* __restrict__ b)
{
    int row = blockIdx.x;
    const float* xr = in + (size_t)row*EE;
    float ls = 0.f, lq = 0.f;
    for (int e = threadIdx.x; e < EE; e += 128) {
        float v = xr[e];
        ls += v;
        lq += v*v;
    }
    #pragma unroll
    for (int o = 16; o > 0; o >>= 1) {
        ls += __shfl_down_sync(0xffffffffu, ls, o);
        lq += __shfl_down_sync(0xffffffffu, lq, o);
    }
    __shared__ float ss[4], sq[4];
    int w = threadIdx.x >> 5, lane = threadIdx.x & 31;
    if (lane == 0) { ss[w] = ls; sq[w] = lq; }
    __syncthreads();
    float tot  = ss[0] + ss[1] + ss[2] + ss[3];
    float totq = sq[0] + sq[1] + sq[2] + sq[3];
    float mean = tot * (1.0f/EE);
    float var  = totq * (1.0f/EE) - mean*mean;
    float inv  = rsqrtf(var + 1e-5f);
    for (int e = threadIdx.x; e < EE; e += 128)
        out[(size_t)row*EE + e] = tf32r((xr[e] - mean) * inv * s[e] + b[e]);
}

// ---------------- tf32 tensor-core GEMM, cp.async 3-stage pipeline ----------------
// Block 128x128, BK=32, 256 threads = 8 warps (4m x 2n), warp tile 32x64.
// Inputs must already be tf32-rounded. Requires M%128==0, N%128==0, K%32==0.
#define NSTAGE 3
#define A_FLOATS (128*36)
#define B_FLOATS (32*128)
#define STAGE_FLOATS (A_FLOATS + B_FLOATS)
#define GEMM_SMEM (NSTAGE*STAGE_FLOATS*4)

template<int RELU, int ACC, int ROUND>
__global__ void __launch_bounds__(256, 2)
tgemm_kernel(const float* __restrict__ A, const float* __restrict__ B,
             const float* __restrict__ bias, float* __restrict__ C,
             int M, int N, int K)
{
    extern __shared__ float smem_f[];
    const uint32_t smem_u = (uint32_t)__cvta_generic_to_shared(smem_f);
    const uint32_t* smem_i = (const uint32_t*)smem_f;

    const int tid  = threadIdx.x;
    const int lane = tid & 31;
    const int wid  = tid >> 5;
    const int wm   = wid & 3;
    const int wn   = wid >> 2;
    const int g    = lane >> 2;
    const int t    = lane & 3;

    const int row0 = blockIdx.y * 128;
    const int col0 = blockIdx.x * 128;

    const int KT = K >> 5;

    int am[4], ak[4], bk[4], bn[4];
    #pragma unroll
    for (int i = 0; i < 4; i++) {
        int c = tid + 256*i;
        am[i] = c >> 3;  ak[i] = (c & 7) * 4;
        bk[i] = c >> 5;  bn[i] = (c & 31) * 4;
    }

    auto issue = [&](int kt) {
        int s = kt % NSTAGE;
        uint32_t a_st = smem_u + (uint32_t)(s * STAGE_FLOATS) * 4u;
        uint32_t b_st = a_st + A_FLOATS * 4u;
        #pragma unroll
        for (int i = 0; i < 4; i++)
            cp_async16(a_st + (uint32_t)(am[i]*36 + ak[i])*4u,
                       A + (size_t)(row0 + am[i]) * K + kt*32 + ak[i]);
        #pragma unroll
        for (int i = 0; i < 4; i++)
            cp_async16(b_st + (uint32_t)(bk[i]*128 + (bn[i] ^ (8*(bk[i]&3))))*4u,
                       B + (size_t)(kt*32 + bk[i]) * N + col0 + bn[i]);
        cp_commit();
    };

    float acc[2][8][4];
    #pragma unroll
    for (int mi = 0; mi < 2; mi++)
        #pragma unroll
        for (int ni = 0; ni < 8; ni++)
            #pragma unroll
            for (int r = 0; r < 4; r++) acc[mi][ni][r] = 0.f;

    issue(0);
    issue(1);

    const int a_off0 = (wm*32 + g)*36 + t;
    const int nbase  = wn*64 + g;

    for (int kt = 0; kt < KT; kt++) {
        cp_wait<NSTAGE-2>();
        __syncthreads();
        if (kt + NSTAGE - 1 < KT) issue(kt + NSTAGE - 1);

        const uint32_t* a_st = smem_i + (kt % NSTAGE) * STAGE_FLOATS;
        const uint32_t* b_st = a_st + A_FLOATS;
        const int sw = 8 * t;

        #pragma unroll
        for (int ks = 0; ks < 4; ks++) {
            const int k0 = ks * 8;
            uint32_t af[2][4], bf[8][2];
            #pragma unroll
            for (int mi = 0; mi < 2; mi++) {
                const uint32_t* ap = a_st + a_off0 + mi*16*36 + k0;
                af[mi][0] = ap[0];
                af[mi][1] = ap[8*36];
                af[mi][2] = ap[4];
                af[mi][3] = ap[8*36 + 4];
            }
            const uint32_t* bp = b_st + (k0 + t)*128;
            #pragma unroll
            for (int ni = 0; ni < 8; ni++) {
                int n = (nbase + ni*8) ^ sw;
                bf[ni][0] = bp[n];
                bf[ni][1] = bp[4*128 + n];
            }
            #pragma unroll
            for (int mi = 0; mi < 2; mi++)
                #pragma unroll
                for (int ni = 0; ni < 8; ni++)
                    mma_tf32(acc[mi][ni], af[mi], bf[ni]);
        }
        __syncthreads();
    }

    // epilogue
    #pragma unroll
    for (int mi = 0; mi < 2; mi++) {
        #pragma unroll
        for (int ni = 0; ni < 8; ni++) {
            int row = row0 + wm*32 + mi*16 + g;
            int col = col0 + wn*64 + ni*8 + t*2;
            float v0 = acc[mi][ni][0], v1 = acc[mi][ni][1];
            float v2 = acc[mi][ni][2], v3 = acc[mi][ni][3];
            if (bias) {
                float b0 = bias[col], b1 = bias[col+1];
                v0 += b0; v1 += b1; v2 += b0; v3 += b1;
            }
            if (RELU) {
                v0 = fmaxf(v0, 0.f); v1 = fmaxf(v1, 0.f);
                v2 = fmaxf(v2, 0.f); v3 = fmaxf(v3, 0.f);
            }
            float* c0 = C + (size_t)row * N + col;
            float* c1 = C + (size_t)(row + 8) * N + col;
            if (ACC) {
                float2 o0 = *(const float2*)c0;
                float2 o1 = *(const float2*)c1;
                v0 += o0.x; v1 += o0.y; v2 += o1.x; v3 += o1.y;
            }
            if (ROUND) {
                v0 = tf32r(v0); v1 = tf32r(v1); v2 = tf32r(v2); v3 = tf32r(v3);
            }
            *(float2*)c0 = make_float2(v0, v1);
            *(float2*)c1 = make_float2(v2, v3);
        }
    }
}

// ---------------- fused causal attention (outputs tf32-rounded) ----------------
__global__ void __launch_bounds__(512)
attn_kernel(const float* __restrict__ qkv, float* __restrict__ o)
{
    extern __shared__ float4 sm4[];
    float4* K4 = sm4;
    float4* V4 = sm4 + TT*16;

    int b = blockIdx.x / HH;
    int h = blockIdx.x % HH;
    int tid = threadIdx.x;

    const float* base = qkv + (size_t)b*TT*E3;
    for (int idx = tid; idx < TT*16; idx += 512) {
        int j  = idx >> 4;
        int d4 = idx & 15;
        K4[idx] = ((const float4*)(base + (size_t)j*E3 + EE   + h*DD))[d4];
        V4[idx] = ((const float4*)(base + (size_t)j*E3 + 2*EE + h*DD))[d4];
    }
    __syncthreads();

    int i = tid >> 1;
    int p = tid & 1;
    const float4* qg = (const float4*)(base + (size_t)i*E3 + h*DD);
    float4 qv[16];
    #pragma unroll
    for (int d4 = 0; d4 < 16; d4++) qv[d4] = qg[d4];

    float4 ov[16];
    #pragma unroll
    for (int d4 = 0; d4 < 16; d4++) ov[d4] = make_float4(0.f, 0.f, 0.f, 0.f);

    float m = -1e30f, lsum = 0.f;
    const float scale = 0.125f;

    for (int j = p; j <= i; j += 2) {
        float4 s4 = make_float4(0.f, 0.f, 0.f, 0.f);
        #pragma unroll
        for (int d4 = 0; d4 < 16; d4++) {
            float4 kk = K4[j*16 + d4];
            s4.x = fmaf(qv[d4].x, kk.x, s4.x);
            s4.y = fmaf(qv[d4].y, kk.y, s4.y);
            s4.z = fmaf(qv[d4].z, kk.z, s4.z);
            s4.w = fmaf(qv[d4].w, kk.w, s4.w);
        }
        float s = ((s4.x + s4.y) + (s4.z + s4.w)) * scale;
        float mn = fmaxf(m, s);
        float c = __expf(m - mn);
        float pw = __expf(s - mn);
        lsum = lsum * c + pw;
        #pragma unroll
        for (int d4 = 0; d4 < 16; d4++) {
            float4 vv = V4[j*16 + d4];
            ov[d4].x = fmaf(ov[d4].x, c, pw*vv.x);
            ov[d4].y = fmaf(ov[d4].y, c, pw*vv.y);
            ov[d4].z = fmaf(ov[d4].z, c, pw*vv.z);
            ov[d4].w = fmaf(ov[d4].w, c, pw*vv.w);
        }
        m = mn;
    }

    float mo = __shfl_xor_sync(0xffffffffu, m, 1);
    float lo = __shfl_xor_sync(0xffffffffu, lsum, 1);
    float mn = fmaxf(m, mo);
    float cs = __expf(m - mn);
    float co = __expf(mo - mn);
    float lm = lsum * cs + lo * co;
    float r = 1.0f / lm;

    float4* og = (float4*)(o + (size_t)(b*TT + i)*EE + h*DD);
    #pragma unroll
    for (int d4 = 0; d4 < 16; d4++) {
        float ox = ov[d4].x*cs + __shfl_xor_sync(0xffffffffu, ov[d4].x, 1)*co;
        float oy = ov[d4].y*cs + __shfl_xor_sync(0xffffffffu, ov[d4].y, 1)*co;
        float oz = ov[d4].z*cs + __shfl_xor_sync(0xffffffffu, ov[d4].z, 1)*co;
        float ow = ov[d4].w*cs + __shfl_xor_sync(0xffffffffu, ov[d4].w, 1)*co;
        if (p == 0)
            og[d4] = make_float4(tf32r(ox*r), tf32r(oy*r), tf32r(oz*r), tf32r(ow*r));
    }
}

// ---------------- launcher ----------------
extern "C" void kernel_launch(void* const* d_in, const int* in_sizes, int n_in,
                              void* d_out, int out_size)
{
    (void)in_sizes; (void)n_in; (void)out_size;
    const int*   idx  = (const int*)  d_in[0];
    const float* tok  = (const float*)d_in[1];
    const float* pos  = (const float*)d_in[2];
    const float* Wq   = (const float*)d_in[3];
    const float* Wk   = (const float*)d_in[4];
    const float* Wv   = (const float*)d_in[5];
    const float* Wo   = (const float*)d_in[6];
    const float* bo   = (const float*)d_in[7];
    const float* ln1s = (const float*)d_in[8];
    const float* ln1b = (const float*)d_in[9];
    const float* ln2s = (const float*)d_in[10];
    const float* ln2b = (const float*)d_in[11];
    const float* W1   = (const float*)d_in[12];
    const float* b1   = (const float*)d_in[13];
    const float* W2   = (const float*)d_in[14];
    const float* b2   = (const float*)d_in[15];
    const float* lnfs = (const float*)d_in[16];
    const float* lnfb = (const float*)d_in[17];
    const float* Wh   = (const float*)d_in[18];
    const float* bh   = (const float*)d_in[19];
    float* out = (float*)d_out;

    float *x, *h, *qkv, *ao, *ff, *wqkv, *wo, *w1, *w2, *wh;
    cudaGetSymbolAddress((void**)&x,    g_x);
    cudaGetSymbolAddress((void**)&h,    g_h);
    cudaGetSymbolAddress((void**)&qkv,  g_qkv);
    cudaGetSymbolAddress((void**)&ao,   g_ao);
    cudaGetSymbolAddress((void**)&ff,   g_ff);
    cudaGetSymbolAddress((void**)&wqkv, g_wqkv);
    cudaGetSymbolAddress((void**)&wo,   g_wo);
    cudaGetSymbolAddress((void**)&w1,   g_w1);
    cudaGetSymbolAddress((void**)&w2,   g_w2);
    cudaGetSymbolAddress((void**)&wh,   g_wh);

    cudaFuncSetAttribute(tgemm_kernel<0,0,0>, cudaFuncAttributeMaxDynamicSharedMemorySize, GEMM_SMEM);
    cudaFuncSetAttribute(tgemm_kernel<0,1,0>, cudaFuncAttributeMaxDynamicSharedMemorySize, GEMM_SMEM);
    cudaFuncSetAttribute(tgemm_kernel<1,0,1>, cudaFuncAttributeMaxDynamicSharedMemorySize, GEMM_SMEM);
    cudaFuncSetAttribute(attn_kernel, cudaFuncAttributeMaxDynamicSharedMemorySize, 131072);

    dim3 blk(256);
    embed_kernel<<<(MM*EE + 255)/256, 256>>>(idx, tok, pos, x);
    pack_qkv_kernel<<<(LL*EE*E3 + 255)/256, 256>>>(Wq, Wk, Wv, wqkv);
    round_copy_kernel<<<(LL*EE*EE + 255)/256, 256>>>(Wo, wo, LL*EE*EE);
    round_copy_kernel<<<(LL*EE*FF + 255)/256, 256>>>(W1, w1, LL*EE*FF);
    round_copy_kernel<<<(LL*FF*EE + 255)/256, 256>>>(W2, w2, LL*FF*EE);
    round_copy_kernel<<<(EE*VVOC  + 255)/256, 256>>>(Wh, wh, EE*VVOC);

    dim3 gQKV(E3/128, MM/128);
    dim3 gE(EE/128, MM/128);
    dim3 gF(FF/128, MM/128);
    dim3 gV(VVOC/128, MM/128);

    for (int l = 0; l < LL; l++) {
        ln_kernel<<<MM, 128>>>(x, h, ln1s + l*EE, ln1b + l*EE);
        tgemm_kernel<0,0,0><<<gQKV, blk, GEMM_SMEM>>>(h, wqkv + (size_t)l*EE*E3, nullptr, qkv, MM, E3, EE);
        attn_kernel<<<BV*HH, 512, 131072>>>(qkv, ao);
        tgemm_kernel<0,1,0><<<gE, blk, GEMM_SMEM>>>(ao, wo + (size_t)l*EE*EE, bo + l*EE, x, MM, EE, EE);
        ln_kernel<<<MM, 128>>>(x, h, ln2s + l*EE, ln2b + l*EE);
        tgemm_kernel<1,0,1><<<gF, blk, GEMM_SMEM>>>(h, w1 + (size_t)l*EE*FF, b1 + l*FF, ff, MM, FF, EE);
        tgemm_kernel<0,1,0><<<gE, blk, GEMM_SMEM>>>(ff, w2 + (size_t)l*FF*EE, b2 + l*EE, x, MM, EE, FF);
    }
    ln_kernel<<<MM, 128>>>(x, h, lnfs, lnfb);
    tgemm_kernel<0,0,0><<<gV, blk, GEMM_SMEM>>>(h, wh, bh, out, MM, VVOC, EE);
}

// round 7
// speedup vs baseline: 3.4666x; 1.3891x over previous
#include <cuda_runtime.h>
#include <cuda_fp16.h>
#include <math.h>
#include <stdint.h>

// Problem constants
#define BV 32
#define TT 256
#define EE 384
#define HH 6
#define DD 64
#define LL 6
#define FF 1536
#define VVOC 32000
#define MM (BV*TT)   // 8192
#define E3 (3*EE)    // 1152

// ---------------- scratch ----------------
__device__ float  g_x   [MM*EE];
__device__ float  g_qkv [MM*E3];
__device__ __half g_h   [MM*EE];
__device__ __half g_ao  [MM*EE];
__device__ __half g_ff  [(size_t)MM*FF];
__device__ __half g_wqkv[LL*EE*E3];
__device__ __half g_wo  [LL*EE*EE];
__device__ __half g_w1  [LL*EE*FF];
__device__ __half g_w2  [LL*FF*EE];
__device__ __half g_wh  [(size_t)EE*VVOC];

// ---------------- PTX helpers ----------------
__device__ __forceinline__ void cp_async16(uint32_t dst, const void* src) {
    asm volatile("cp.async.cg.shared.global [%0], [%1], 16;" :: "r"(dst), "l"(src));
}
__device__ __forceinline__ void cp_commit() { asm volatile("cp.async.commit_group;"); }
template<int N>
__device__ __forceinline__ void cp_wait() { asm volatile("cp.async.wait_group %0;" :: "n"(N)); }

__device__ __forceinline__ void ldsm_x4(uint32_t* r, uint32_t a) {
    asm volatile("ldmatrix.sync.aligned.m8n8.x4.shared.b16 {%0,%1,%2,%3}, [%4];"
        : "=r"(r[0]), "=r"(r[1]), "=r"(r[2]), "=r"(r[3]) : "r"(a));
}
__device__ __forceinline__ void ldsm_x4_t(uint32_t* r, uint32_t a) {
    asm volatile("ldmatrix.sync.aligned.m8n8.x4.trans.shared.b16 {%0,%1,%2,%3}, [%4];"
        : "=r"(r[0]), "=r"(r[1]), "=r"(r[2]), "=r"(r[3]) : "r"(a));
}
__device__ __forceinline__ void mma_f16(float* c, const uint32_t* a, const uint32_t* b) {
    asm volatile(
        "mma.sync.aligned.m16n8k16.row.col.f32.f16.f16.f32 "
        "{%0,%1,%2,%3}, {%4,%5,%6,%7}, {%8,%9}, {%0,%1,%2,%3};"
        : "+f"(c[0]), "+f"(c[1]), "+f"(c[2]), "+f"(c[3])
        : "r"(a[0]), "r"(a[1]), "r"(a[2]), "r"(a[3]), "r"(b[0]), "r"(b[1]));
}

// ---------------- embedding ----------------
__global__ void embed_kernel(const int* __restrict__ idx, const float* __restrict__ tok,
                             const float* __restrict__ pos, float* __restrict__ x)
{
    int i = blockIdx.x * blockDim.x + threadIdx.x;
    if (i >= MM*EE) return;
    int e   = i % EE;
    int row = i / EE;
    int t   = row % TT;
    x[i] = tok[(size_t)idx[row]*EE + e] + pos[t*EE + e];
}

// ---------------- weight prep ----------------
__global__ void to_half_kernel(const float* __restrict__ src, __half* __restrict__ dst, int n)
{
    int i = blockIdx.x * blockDim.x + threadIdx.x;
    if (i < n) dst[i] = __float2half_rn(src[i]);
}

__global__ void pack_qkv_half(const float* __restrict__ Wq, const float* __restrict__ Wk,
                              const float* __restrict__ Wv, __half* __restrict__ out)
{
    int i = blockIdx.x * blockDim.x + threadIdx.x;
    if (i >= LL*EE*E3) return;
    int c  = i % E3;
    int re = i / E3;        // l*EE + e
    int sel = c / EE;
    int cc  = c % EE;
    const float* src = (sel == 0) ? Wq : (sel == 1) ? Wk : Wv;
    out[i] = __float2half_rn(src[(size_t)re*EE + cc]);
}

// ---------------- layernorm -> fp16 ----------------
__global__ void ln_kernel(const float* __restrict__ in, __half* __restrict__ out,
                          const float* __restrict__ s, const float* __restrict__ b)
{
    int row = blockIdx.x;
    const float* xr = in + (size_t)row*EE;
    float ls = 0.f, lq = 0.f;
    for (int e = threadIdx.x; e < EE; e += 128) {
        float v = xr[e];
        ls += v; lq += v*v;
    }
    #pragma unroll
    for (int o = 16; o > 0; o >>= 1) {
        ls += __shfl_down_sync(0xffffffffu, ls, o);
        lq += __shfl_down_sync(0xffffffffu, lq, o);
    }
    __shared__ float ss[4], sq[4];
    int w = threadIdx.x >> 5, lane = threadIdx.x & 31;
    if (lane == 0) { ss[w] = ls; sq[w] = lq; }
    __syncthreads();
    float tot  = ss[0] + ss[1] + ss[2] + ss[3];
    float totq = sq[0] + sq[1] + sq[2] + sq[3];
    float mean = tot * (1.0f/EE);
    float var  = totq * (1.0f/EE) - mean*mean;
    float inv  = rsqrtf(var + 1e-5f);
    for (int e = threadIdx.x; e < EE; e += 128)
        out[(size_t)row*EE + e] = __float2half_rn((xr[e] - mean) * inv * s[e] + b[e]);
}

// ---------------- fp16 tensor-core GEMM, 5-stage cp.async + ldmatrix ----------------
// C[M,N] op= A[M,K] @ B[K,N] (+bias). A,B fp16; accum f32.
// Block 128x128, BK=32, 256 threads = 8 warps (4m x 2n), warp tile 32x64, mma m16n8k16.
// MODE: 0 = f32 store, 1 = f32 accumulate into C, 2 = relu -> fp16 store
#define NST 5
#define ATILE 8192           // 128 rows * 32 halves * 2B
#define BTILE 8192           // 32 rows * 128 halves * 2B
#define STAGE (ATILE + BTILE)
#define GEMM_SMEM (NST*STAGE)

template<int MODE>
__global__ void __launch_bounds__(256, 2)
hgemm_kernel(const __half* __restrict__ A, const __half* __restrict__ B,
             const float* __restrict__ bias, void* __restrict__ Cv,
             int M, int N, int K)
{
    extern __shared__ char smem[];
    const uint32_t sb = (uint32_t)__cvta_generic_to_shared(smem);

    const int tid  = threadIdx.x;
    const int lane = tid & 31;
    const int wid  = tid >> 5;
    const int wm   = wid & 3;
    const int wn   = wid >> 2;
    const int g    = lane >> 2;
    const int t    = lane & 3;

    const int row0 = blockIdx.y * 128;
    const int col0 = blockIdx.x * 128;
    const int KT   = K >> 5;

    auto issue = [&](int kt) {
        uint32_t st = sb + (uint32_t)(kt % NST) * STAGE;
        #pragma unroll
        for (int i = 0; i < 2; i++) {          // A: 512 16B chunks
            int c = tid + 256*i;
            int r = c >> 2, gg = c & 3;
            cp_async16(st + r*64 + 16*(gg ^ ((r>>1)&3)),
                       A + (size_t)(row0 + r)*K + kt*32 + gg*8);
        }
        #pragma unroll
        for (int i = 0; i < 2; i++) {          // B: 512 16B chunks
            int c = tid + 256*i;
            int k = c >> 4, gg = c & 15;
            cp_async16(st + ATILE + k*256 + 16*(gg ^ (k&7)),
                       B + (size_t)(kt*32 + k)*N + col0 + gg*8);
        }
        cp_commit();
    };

    float acc[2][8][4];
    #pragma unroll
    for (int mi = 0; mi < 2; mi++)
        #pragma unroll
        for (int ni = 0; ni < 8; ni++)
            #pragma unroll
            for (int r = 0; r < 4; r++) acc[mi][ni][r] = 0.f;

    issue(0); issue(1); issue(2); issue(3);

    for (int kt = 0; kt < KT; kt++) {
        cp_wait<3>();
        __syncthreads();
        if (kt + 4 < KT) issue(kt + 4);

        const uint32_t a_st = sb + (uint32_t)(kt % NST) * STAGE;
        const uint32_t b_st = a_st + ATILE;

        #pragma unroll
        for (int ks = 0; ks < 2; ks++) {
            uint32_t af[2][4], bf[8][2];
            #pragma unroll
            for (int mi = 0; mi < 2; mi++) {
                int m  = wm*32 + mi*16 + (lane & 15);
                int gg = ks*2 + (lane >> 4);
                ldsm_x4(af[mi], a_st + m*64 + 16*(gg ^ ((m>>1)&3)));
            }
            #pragma unroll
            for (int np = 0; np < 4; np++) {
                int k  = ks*16 + (lane & 15);
                int gg = (wn*64 + np*16)/8 + (lane >> 4);
                uint32_t tmp[4];
                ldsm_x4_t(tmp, b_st + k*256 + 16*(gg ^ (k&7)));
                bf[np*2][0]   = tmp[0]; bf[np*2][1]   = tmp[1];
                bf[np*2+1][0] = tmp[2]; bf[np*2+1][1] = tmp[3];
            }
            #pragma unroll
            for (int mi = 0; mi < 2; mi++)
                #pragma unroll
                for (int ni = 0; ni < 8; ni++)
                    mma_f16(acc[mi][ni], af[mi], bf[ni]);
        }
        __syncthreads();
    }

    // epilogue
    #pragma unroll
    for (int mi = 0; mi < 2; mi++) {
        #pragma unroll
        for (int ni = 0; ni < 8; ni++) {
            int row = row0 + wm*32 + mi*16 + g;
            int col = col0 + wn*64 + ni*8 + t*2;
            float v0 = acc[mi][ni][0], v1 = acc[mi][ni][1];
            float v2 = acc[mi][ni][2], v3 = acc[mi][ni][3];
            if (bias) {
                float b0 = bias[col], b1 = bias[col+1];
                v0 += b0; v1 += b1; v2 += b0; v3 += b1;
            }
            if (MODE == 2) {
                v0 = fmaxf(v0, 0.f); v1 = fmaxf(v1, 0.f);
                v2 = fmaxf(v2, 0.f); v3 = fmaxf(v3, 0.f);
                __half* C = (__half*)Cv;
                *(__half2*)(C + (size_t)row * N + col)     = __floats2half2_rn(v0, v1);
                *(__half2*)(C + (size_t)(row+8) * N + col) = __floats2half2_rn(v2, v3);
            } else {
                float* C = (float*)Cv;
                float* c0 = C + (size_t)row * N + col;
                float* c1 = C + (size_t)(row + 8) * N + col;
                if (MODE == 1) {
                    float2 o0 = *(const float2*)c0;
                    float2 o1 = *(const float2*)c1;
                    v0 += o0.x; v1 += o0.y; v2 += o1.x; v3 += o1.y;
                }
                *(float2*)c0 = make_float2(v0, v1);
                *(float2*)c1 = make_float2(v2, v3);
            }
        }
    }
}

// ---------------- fused causal attention (fp32 in, fp16 out) ----------------
__global__ void __launch_bounds__(512)
attn_kernel(const float* __restrict__ qkv, __half* __restrict__ o)
{
    extern __shared__ float4 sm4[];
    float4* K4 = sm4;
    float4* V4 = sm4 + TT*16;

    int b = blockIdx.x / HH;
    int h = blockIdx.x % HH;
    int tid = threadIdx.x;

    const float* base = qkv + (size_t)b*TT*E3;
    for (int idx = tid; idx < TT*16; idx += 512) {
        int j  = idx >> 4;
        int d4 = idx & 15;
        K4[idx] = ((const float4*)(base + (size_t)j*E3 + EE   + h*DD))[d4];
        V4[idx] = ((const float4*)(base + (size_t)j*E3 + 2*EE + h*DD))[d4];
    }
    __syncthreads();

    int i = tid >> 1;
    int p = tid & 1;
    const float4* qg = (const float4*)(base + (size_t)i*E3 + h*DD);
    float4 qv[16];
    #pragma unroll
    for (int d4 = 0; d4 < 16; d4++) qv[d4] = qg[d4];

    float4 ov[16];
    #pragma unroll
    for (int d4 = 0; d4 < 16; d4++) ov[d4] = make_float4(0.f, 0.f, 0.f, 0.f);

    float m = -1e30f, lsum = 0.f;
    const float scale = 0.125f;

    for (int j = p; j <= i; j += 2) {
        float4 s4 = make_float4(0.f, 0.f, 0.f, 0.f);
        #pragma unroll
        for (int d4 = 0; d4 < 16; d4++) {
            float4 kk = K4[j*16 + d4];
            s4.x = fmaf(qv[d4].x, kk.x, s4.x);
            s4.y = fmaf(qv[d4].y, kk.y, s4.y);
            s4.z = fmaf(qv[d4].z, kk.z, s4.z);
            s4.w = fmaf(qv[d4].w, kk.w, s4.w);
        }
        float s = ((s4.x + s4.y) + (s4.z + s4.w)) * scale;
        float mn = fmaxf(m, s);
        float c = __expf(m - mn);
        float pw = __expf(s - mn);
        lsum = lsum * c + pw;
        #pragma unroll
        for (int d4 = 0; d4 < 16; d4++) {
            float4 vv = V4[j*16 + d4];
            ov[d4].x = fmaf(ov[d4].x, c, pw*vv.x);
            ov[d4].y = fmaf(ov[d4].y, c, pw*vv.y);
            ov[d4].z = fmaf(ov[d4].z, c, pw*vv.z);
            ov[d4].w = fmaf(ov[d4].w, c, pw*vv.w);
        }
        m = mn;
    }

    float mo = __shfl_xor_sync(0xffffffffu, m, 1);
    float lo = __shfl_xor_sync(0xffffffffu, lsum, 1);
    float mn = fmaxf(m, mo);
    float cs = __expf(m - mn);
    float co = __expf(mo - mn);
    float lm = lsum * cs + lo * co;
    float r = 1.0f / lm;

    __half* oh = o + (size_t)(b*TT + i)*EE + h*DD;
    #pragma unroll
    for (int d4 = 0; d4 < 16; d4++) {
        float ox = (ov[d4].x*cs + __shfl_xor_sync(0xffffffffu, ov[d4].x, 1)*co) * r;
        float oy = (ov[d4].y*cs + __shfl_xor_sync(0xffffffffu, ov[d4].y, 1)*co) * r;
        float oz = (ov[d4].z*cs + __shfl_xor_sync(0xffffffffu, ov[d4].z, 1)*co) * r;
        float ow = (ov[d4].w*cs + __shfl_xor_sync(0xffffffffu, ov[d4].w, 1)*co) * r;
        if (p == 0) {
            *(__half2*)(oh + d4*4)     = __floats2half2_rn(ox, oy);
            *(__half2*)(oh + d4*4 + 2) = __floats2half2_rn(oz, ow);
        }
    }
}

// ---------------- launcher ----------------
extern "C" void kernel_launch(void* const* d_in, const int* in_sizes, int n_in,
                              void* d_out, int out_size)
{
    (void)in_sizes; (void)n_in; (void)out_size;
    const int*   idx  = (const int*)  d_in[0];
    const float* tok  = (const float*)d_in[1];
    const float* pos  = (const float*)d_in[2];
    const float* Wq   = (const float*)d_in[3];
    const float* Wk   = (const float*)d_in[4];
    const float* Wv   = (const float*)d_in[5];
    const float* Wo   = (const float*)d_in[6];
    const float* bo   = (const float*)d_in[7];
    const float* ln1s = (const float*)d_in[8];
    const float* ln1b = (const float*)d_in[9];
    const float* ln2s = (const float*)d_in[10];
    const float* ln2b = (const float*)d_in[11];
    const float* W1   = (const float*)d_in[12];
    const float* b1   = (const float*)d_in[13];
    const float* W2   = (const float*)d_in[14];
    const float* b2   = (const float*)d_in[15];
    const float* lnfs = (const float*)d_in[16];
    const float* lnfb = (const float*)d_in[17];
    const float* Wh   = (const float*)d_in[18];
    const float* bh   = (const float*)d_in[19];
    float* out = (float*)d_out;

    float *x, *qkv;
    __half *h, *ao, *ff, *wqkv, *wo, *w1, *w2, *wh;
    cudaGetSymbolAddress((void**)&x,    g_x);
    cudaGetSymbolAddress((void**)&qkv,  g_qkv);
    cudaGetSymbolAddress((void**)&h,    g_h);
    cudaGetSymbolAddress((void**)&ao,   g_ao);
    cudaGetSymbolAddress((void**)&ff,   g_ff);
    cudaGetSymbolAddress((void**)&wqkv, g_wqkv);
    cudaGetSymbolAddress((void**)&wo,   g_wo);
    cudaGetSymbolAddress((void**)&w1,   g_w1);
    cudaGetSymbolAddress((void**)&w2,   g_w2);
    cudaGetSymbolAddress((void**)&wh,   g_wh);

    cudaFuncSetAttribute(hgemm_kernel<0>, cudaFuncAttributeMaxDynamicSharedMemorySize, GEMM_SMEM);
    cudaFuncSetAttribute(hgemm_kernel<1>, cudaFuncAttributeMaxDynamicSharedMemorySize, GEMM_SMEM);
    cudaFuncSetAttribute(hgemm_kernel<2>, cudaFuncAttributeMaxDynamicSharedMemorySize, GEMM_SMEM);
    cudaFuncSetAttribute(attn_kernel, cudaFuncAttributeMaxDynamicSharedMemorySize, 131072);

    embed_kernel<<<(MM*EE + 255)/256, 256>>>(idx, tok, pos, x);
    pack_qkv_half<<<(LL*EE*E3 + 255)/256, 256>>>(Wq, Wk, Wv, wqkv);
    to_half_kernel<<<(LL*EE*EE + 255)/256, 256>>>(Wo, wo, LL*EE*EE);
    to_half_kernel<<<(LL*EE*FF + 255)/256, 256>>>(W1, w1, LL*EE*FF);
    to_half_kernel<<<(LL*FF*EE + 255)/256, 256>>>(W2, w2, LL*FF*EE);
    to_half_kernel<<<(EE*VVOC  + 255)/256, 256>>>(Wh, wh, EE*VVOC);

    dim3 blk(256);
    dim3 gQKV(E3/128, MM/128);   // 9 x 64
    dim3 gE(EE/128, MM/128);     // 3 x 64
    dim3 gF(FF/128, MM/128);     // 12 x 64
    dim3 gV(VVOC/128, MM/128);   // 250 x 64

    for (int l = 0; l < LL; l++) {
        ln_kernel<<<MM, 128>>>(x, h, ln1s + l*EE, ln1b + l*EE);
        hgemm_kernel<0><<<gQKV, blk, GEMM_SMEM>>>(h, wqkv + (size_t)l*EE*E3, nullptr, qkv, MM, E3, EE);
        attn_kernel<<<BV*HH, 512, 131072>>>(qkv, ao);
        hgemm_kernel<1><<<gE, blk, GEMM_SMEM>>>(ao, wo + (size_t)l*EE*EE, bo + l*EE, x, MM, EE, EE);
        ln_kernel<<<MM, 128>>>(x, h, ln2s + l*EE, ln2b + l*EE);
        hgemm_kernel<2><<<gF, blk, GEMM_SMEM>>>(h, w1 + (size_t)l*EE*FF, b1 + l*FF, ff, MM, FF, EE);
        hgemm_kernel<1><<<gE, blk, GEMM_SMEM>>>(ff, w2 + (size_t)l*FF*EE, b2 + l*EE, x, MM, EE, FF);
    }
    ln_kernel<<<MM, 128>>>(x, h, lnfs, lnfb);
    hgemm_kernel<0><<<gV, blk, GEMM_SMEM>>>(h, wh, bh, out, MM, VVOC, EE);
}

// round 8
// speedup vs baseline: 3.5310x; 1.0186x over previous
#include <cuda_runtime.h>
#include <cuda_fp16.h>
#include <math.h>
#include <stdint.h>

// Problem constants
#define BV 32
#define TT 256
#define EE 384
#define HH 6
#define DD 64
#define LL 6
#define FF 1536
#define VVOC 32000
#define MM (BV*TT)   // 8192
#define E3 (3*EE)    // 1152

// ---------------- scratch ----------------
__device__ float  g_x   [MM*EE];
__device__ float  g_qkv [MM*E3];
__device__ __half g_h   [MM*EE];
__device__ __half g_ao  [MM*EE];
__device__ __half g_ff  [(size_t)MM*FF];
__device__ __half g_wqkv[LL*EE*E3];
__device__ __half g_wo  [LL*EE*EE];
__device__ __half g_w1  [LL*EE*FF];
__device__ __half g_w2  [LL*FF*EE];
__device__ __half g_wh  [(size_t)EE*VVOC];

// ---------------- PTX helpers ----------------
__device__ __forceinline__ void cp_async16(uint32_t dst, const void* src) {
    asm volatile("cp.async.cg.shared.global [%0], [%1], 16;" :: "r"(dst), "l"(src));
}
__device__ __forceinline__ void cp_commit() { asm volatile("cp.async.commit_group;"); }
template<int N>
__device__ __forceinline__ void cp_wait() { asm volatile("cp.async.wait_group %0;" :: "n"(N)); }

__device__ __forceinline__ void ldsm_x4(uint32_t* r, uint32_t a) {
    asm volatile("ldmatrix.sync.aligned.m8n8.x4.shared.b16 {%0,%1,%2,%3}, [%4];"
        : "=r"(r[0]), "=r"(r[1]), "=r"(r[2]), "=r"(r[3]) : "r"(a));
}
__device__ __forceinline__ void ldsm_x4_t(uint32_t* r, uint32_t a) {
    asm volatile("ldmatrix.sync.aligned.m8n8.x4.trans.shared.b16 {%0,%1,%2,%3}, [%4];"
        : "=r"(r[0]), "=r"(r[1]), "=r"(r[2]), "=r"(r[3]) : "r"(a));
}
__device__ __forceinline__ void mma_f16(float* c, const uint32_t* a, const uint32_t* b) {
    asm volatile(
        "mma.sync.aligned.m16n8k16.row.col.f32.f16.f16.f32 "
        "{%0,%1,%2,%3}, {%4,%5,%6,%7}, {%8,%9}, {%0,%1,%2,%3};"
        : "+f"(c[0]), "+f"(c[1]), "+f"(c[2]), "+f"(c[3])
        : "r"(a[0]), "r"(a[1]), "r"(a[2]), "r"(a[3]), "r"(b[0]), "r"(b[1]));
}

// ---------------- embedding ----------------
__global__ void embed_kernel(const int* __restrict__ idx, const float* __restrict__ tok,
                             const float* __restrict__ pos, float* __restrict__ x)
{
    int i = blockIdx.x * blockDim.x + threadIdx.x;
    if (i >= MM*EE) return;
    int e   = i % EE;
    int row = i / EE;
    int t   = row % TT;
    x[i] = tok[(size_t)idx[row]*EE + e] + pos[t*EE + e];
}

// ---------------- weight prep ----------------
__global__ void to_half_kernel(const float* __restrict__ src, __half* __restrict__ dst, int n)
{
    int i = blockIdx.x * blockDim.x + threadIdx.x;
    if (i < n) dst[i] = __float2half_rn(src[i]);
}

__global__ void pack_qkv_half(const float* __restrict__ Wq, const float* __restrict__ Wk,
                              const float* __restrict__ Wv, __half* __restrict__ out)
{
    int i = blockIdx.x * blockDim.x + threadIdx.x;
    if (i >= LL*EE*E3) return;
    int c  = i % E3;
    int re = i / E3;
    int sel = c / EE;
    int cc  = c % EE;
    const float* src = (sel == 0) ? Wq : (sel == 1) ? Wk : Wv;
    out[i] = __float2half_rn(src[(size_t)re*EE + cc]);
}

// ---------------- layernorm -> fp16 (vectorized) ----------------
__global__ void ln_kernel(const float* __restrict__ in, __half* __restrict__ out,
                          const float* __restrict__ s, const float* __restrict__ b)
{
    int row = blockIdx.x;
    const float4* xr = (const float4*)(in + (size_t)row*EE);
    int tid = threadIdx.x;
    float4 v4 = make_float4(0.f,0.f,0.f,0.f);
    if (tid < 96) v4 = xr[tid];
    float ls = (v4.x + v4.y) + (v4.z + v4.w);
    float lq = (v4.x*v4.x + v4.y*v4.y) + (v4.z*v4.z + v4.w*v4.w);
    #pragma unroll
    for (int o = 16; o > 0; o >>= 1) {
        ls += __shfl_down_sync(0xffffffffu, ls, o);
        lq += __shfl_down_sync(0xffffffffu, lq, o);
    }
    __shared__ float ss[4], sq[4];
    int w = tid >> 5, lane = tid & 31;
    if (lane == 0) { ss[w] = ls; sq[w] = lq; }
    __syncthreads();
    float tot  = ss[0] + ss[1] + ss[2] + ss[3];
    float totq = sq[0] + sq[1] + sq[2] + sq[3];
    float mean = tot * (1.0f/EE);
    float var  = totq * (1.0f/EE) - mean*mean;
    float inv  = rsqrtf(var + 1e-5f);
    if (tid < 96) {
        const float4 s4 = ((const float4*)s)[tid];
        const float4 b4 = ((const float4*)b)[tid];
        float o0 = (v4.x - mean) * inv * s4.x + b4.x;
        float o1 = (v4.y - mean) * inv * s4.y + b4.y;
        float o2 = (v4.z - mean) * inv * s4.z + b4.z;
        float o3 = (v4.w - mean) * inv * s4.w + b4.w;
        __half2* op = (__half2*)(out + (size_t)row*EE + tid*4);
        op[0] = __floats2half2_rn(o0, o1);
        op[1] = __floats2half2_rn(o2, o3);
    }
}

// ---------------- fp16 tensor-core GEMM, BK=64, 3-stage cp.async + ldmatrix ----------------
// C[M,N] op= A[M,K] @ B[K,N] (+bias). A,B fp16; accum f32.
// Block 128x128, BK=64, 256 threads = 8 warps (4m x 2n), warp tile 32x64, mma m16n8k16.
// MODE: 0 = f32 store, 1 = f32 accumulate into C, 2 = relu -> fp16 store
#define NST 3
#define ATILE 16384          // 128 rows * 64 halves * 2B
#define BTILE 16384          // 64 rows * 128 halves * 2B
#define STAGE (ATILE + BTILE)
#define GEMM_SMEM (NST*STAGE)

template<int MODE>
__global__ void __launch_bounds__(256, 2)
hgemm_kernel(const __half* __restrict__ A, const __half* __restrict__ B,
             const float* __restrict__ bias, void* __restrict__ Cv,
             int M, int N, int K)
{
    extern __shared__ char smem[];
    const uint32_t sb = (uint32_t)__cvta_generic_to_shared(smem);

    const int tid  = threadIdx.x;
    const int lane = tid & 31;
    const int wid  = tid >> 5;
    const int wm   = wid & 3;
    const int wn   = wid >> 2;
    const int g    = lane >> 2;
    const int t    = lane & 3;

    const int row0 = blockIdx.y * 128;
    const int col0 = blockIdx.x * 128;
    const int KT   = K >> 6;

    auto issue = [&](int kt) {
        uint32_t st = sb + (uint32_t)(kt % NST) * STAGE;
        #pragma unroll
        for (int i = 0; i < 4; i++) {          // A: 1024 16B chunks (128 rows x 8)
            int c = tid + 256*i;
            int r = c >> 3, gg = c & 7;
            cp_async16(st + r*128 + 16*(gg ^ (r&7)),
                       A + (size_t)(row0 + r)*K + kt*64 + gg*8);
        }
        #pragma unroll
        for (int i = 0; i < 4; i++) {          // B: 1024 16B chunks (64 rows x 16)
            int c = tid + 256*i;
            int k = c >> 4, gg = c & 15;
            cp_async16(st + ATILE + k*256 + 16*(gg ^ (k&7)),
                       B + (size_t)(kt*64 + k)*N + col0 + gg*8);
        }
        cp_commit();
    };

    float acc[2][8][4];
    #pragma unroll
    for (int mi = 0; mi < 2; mi++)
        #pragma unroll
        for (int ni = 0; ni < 8; ni++)
            #pragma unroll
            for (int r = 0; r < 4; r++) acc[mi][ni][r] = 0.f;

    issue(0); issue(1);

    for (int kt = 0; kt < KT; kt++) {
        cp_wait<1>();
        __syncthreads();
        if (kt + 2 < KT) issue(kt + 2);

        const uint32_t a_st = sb + (uint32_t)(kt % NST) * STAGE;
        const uint32_t b_st = a_st + ATILE;

        #pragma unroll
        for (int ks = 0; ks < 4; ks++) {
            uint32_t af[2][4], bf[8][2];
            #pragma unroll
            for (int mi = 0; mi < 2; mi++) {
                int m  = wm*32 + mi*16 + (lane & 15);
                int gg = ks*2 + (lane >> 4);
                ldsm_x4(af[mi], a_st + m*128 + 16*(gg ^ (m&7)));
            }
            #pragma unroll
            for (int np = 0; np < 4; np++) {
                int k  = ks*16 + (lane & 15);
                int gg = (wn*64 + np*16)/8 + (lane >> 4);
                uint32_t tmp[4];
                ldsm_x4_t(tmp, b_st + k*256 + 16*(gg ^ (k&7)));
                bf[np*2][0]   = tmp[0]; bf[np*2][1]   = tmp[1];
                bf[np*2+1][0] = tmp[2]; bf[np*2+1][1] = tmp[3];
            }
            #pragma unroll
            for (int mi = 0; mi < 2; mi++)
                #pragma unroll
                for (int ni = 0; ni < 8; ni++)
                    mma_f16(acc[mi][ni], af[mi], bf[ni]);
        }
        __syncthreads();
    }

    // epilogue
    #pragma unroll
    for (int mi = 0; mi < 2; mi++) {
        #pragma unroll
        for (int ni = 0; ni < 8; ni++) {
            int row = row0 + wm*32 + mi*16 + g;
            int col = col0 + wn*64 + ni*8 + t*2;
            float v0 = acc[mi][ni][0], v1 = acc[mi][ni][1];
            float v2 = acc[mi][ni][2], v3 = acc[mi][ni][3];
            if (bias) {
                float b0 = bias[col], b1 = bias[col+1];
                v0 += b0; v1 += b1; v2 += b0; v3 += b1;
            }
            if (MODE == 2) {
                v0 = fmaxf(v0, 0.f); v1 = fmaxf(v1, 0.f);
                v2 = fmaxf(v2, 0.f); v3 = fmaxf(v3, 0.f);
                __half* C = (__half*)Cv;
                *(__half2*)(C + (size_t)row * N + col)     = __floats2half2_rn(v0, v1);
                *(__half2*)(C + (size_t)(row+8) * N + col) = __floats2half2_rn(v2, v3);
            } else {
                float* C = (float*)Cv;
                float* c0 = C + (size_t)row * N + col;
                float* c1 = C + (size_t)(row + 8) * N + col;
                if (MODE == 1) {
                    float2 o0 = *(const float2*)c0;
                    float2 o1 = *(const float2*)c1;
                    v0 += o0.x; v1 += o0.y; v2 += o1.x; v3 += o1.y;
                }
                *(float2*)c0 = make_float2(v0, v1);
                *(float2*)c1 = make_float2(v2, v3);
            }
        }
    }
}

// ---------------- fused causal attention (fp32 in, fp16 out) ----------------
__global__ void __launch_bounds__(512)
attn_kernel(const float* __restrict__ qkv, __half* __restrict__ o)
{
    extern __shared__ float4 sm4[];
    float4* K4 = sm4;
    float4* V4 = sm4 + TT*16;

    int b = blockIdx.x / HH;
    int h = blockIdx.x % HH;
    int tid = threadIdx.x;

    const float* base = qkv + (size_t)b*TT*E3;
    for (int idx = tid; idx < TT*16; idx += 512) {
        int j  = idx >> 4;
        int d4 = idx & 15;
        K4[idx] = ((const float4*)(base + (size_t)j*E3 + EE   + h*DD))[d4];
        V4[idx] = ((const float4*)(base + (size_t)j*E3 + 2*EE + h*DD))[d4];
    }
    __syncthreads();

    int i = tid >> 1;
    int p = tid & 1;
    const float4* qg = (const float4*)(base + (size_t)i*E3 + h*DD);
    float4 qv[16];
    #pragma unroll
    for (int d4 = 0; d4 < 16; d4++) qv[d4] = qg[d4];

    float4 ov[16];
    #pragma unroll
    for (int d4 = 0; d4 < 16; d4++) ov[d4] = make_float4(0.f, 0.f, 0.f, 0.f);

    float m = -1e30f, lsum = 0.f;
    const float scale = 0.125f;

    for (int j = p; j <= i; j += 2) {
        float4 s4 = make_float4(0.f, 0.f, 0.f, 0.f);
        #pragma unroll
        for (int d4 = 0; d4 < 16; d4++) {
            float4 kk = K4[j*16 + d4];
            s4.x = fmaf(qv[d4].x, kk.x, s4.x);
            s4.y = fmaf(qv[d4].y, kk.y, s4.y);
            s4.z = fmaf(qv[d4].z, kk.z, s4.z);
            s4.w = fmaf(qv[d4].w, kk.w, s4.w);
        }
        float s = ((s4.x + s4.y) + (s4.z + s4.w)) * scale;
        float mn = fmaxf(m, s);
        float c = __expf(m - mn);
        float pw = __expf(s - mn);
        lsum = lsum * c + pw;
        #pragma unroll
        for (int d4 = 0; d4 < 16; d4++) {
            float4 vv = V4[j*16 + d4];
            ov[d4].x = fmaf(ov[d4].x, c, pw*vv.x);
            ov[d4].y = fmaf(ov[d4].y, c, pw*vv.y);
            ov[d4].z = fmaf(ov[d4].z, c, pw*vv.z);
            ov[d4].w = fmaf(ov[d4].w, c, pw*vv.w);
        }
        m = mn;
    }

    float mo = __shfl_xor_sync(0xffffffffu, m, 1);
    float lo = __shfl_xor_sync(0xffffffffu, lsum, 1);
    float mn = fmaxf(m, mo);
    float cs = __expf(m - mn);
    float co = __expf(mo - mn);
    float lm = lsum * cs + lo * co;
    float r = 1.0f / lm;

    __half* oh = o + (size_t)(b*TT + i)*EE + h*DD;
    #pragma unroll
    for (int d4 = 0; d4 < 16; d4++) {
        float ox = (ov[d4].x*cs + __shfl_xor_sync(0xffffffffu, ov[d4].x, 1)*co) * r;
        float oy = (ov[d4].y*cs + __shfl_xor_sync(0xffffffffu, ov[d4].y, 1)*co) * r;
        float oz = (ov[d4].z*cs + __shfl_xor_sync(0xffffffffu, ov[d4].z, 1)*co) * r;
        float ow = (ov[d4].w*cs + __shfl_xor_sync(0xffffffffu, ov[d4].w, 1)*co) * r;
        if (p == 0) {
            *(__half2*)(oh + d4*4)     = __floats2half2_rn(ox, oy);
            *(__half2*)(oh + d4*4 + 2) = __floats2half2_rn(oz, ow);
        }
    }
}

// ---------------- launcher ----------------
extern "C" void kernel_launch(void* const* d_in, const int* in_sizes, int n_in,
                              void* d_out, int out_size)
{
    (void)in_sizes; (void)n_in; (void)out_size;
    const int*   idx  = (const int*)  d_in[0];
    const float* tok  = (const float*)d_in[1];
    const float* pos  = (const float*)d_in[2];
    const float* Wq   = (const float*)d_in[3];
    const float* Wk   = (const float*)d_in[4];
    const float* Wv   = (const float*)d_in[5];
    const float* Wo   = (const float*)d_in[6];
    const float* bo   = (const float*)d_in[7];
    const float* ln1s = (const float*)d_in[8];
    const float* ln1b = (const float*)d_in[9];
    const float* ln2s = (const float*)d_in[10];
    const float* ln2b = (const float*)d_in[11];
    const float* W1   = (const float*)d_in[12];
    const float* b1   = (const float*)d_in[13];
    const float* W2   = (const float*)d_in[14];
    const float* b2   = (const float*)d_in[15];
    const float* lnfs = (const float*)d_in[16];
    const float* lnfb = (const float*)d_in[17];
    const float* Wh   = (const float*)d_in[18];
    const float* bh   = (const float*)d_in[19];
    float* out = (float*)d_out;

    float *x, *qkv;
    __half *h, *ao, *ff, *wqkv, *wo, *w1, *w2, *wh;
    cudaGetSymbolAddress((void**)&x,    g_x);
    cudaGetSymbolAddress((void**)&qkv,  g_qkv);
    cudaGetSymbolAddress((void**)&h,    g_h);
    cudaGetSymbolAddress((void**)&ao,   g_ao);
    cudaGetSymbolAddress((void**)&ff,   g_ff);
    cudaGetSymbolAddress((void**)&wqkv, g_wqkv);
    cudaGetSymbolAddress((void**)&wo,   g_wo);
    cudaGetSymbolAddress((void**)&w1,   g_w1);
    cudaGetSymbolAddress((void**)&w2,   g_w2);
    cudaGetSymbolAddress((void**)&wh,   g_wh);

    cudaFuncSetAttribute(hgemm_kernel<0>, cudaFuncAttributeMaxDynamicSharedMemorySize, GEMM_SMEM);
    cudaFuncSetAttribute(hgemm_kernel<1>, cudaFuncAttributeMaxDynamicSharedMemorySize, GEMM_SMEM);
    cudaFuncSetAttribute(hgemm_kernel<2>, cudaFuncAttributeMaxDynamicSharedMemorySize, GEMM_SMEM);
    cudaFuncSetAttribute(attn_kernel, cudaFuncAttributeMaxDynamicSharedMemorySize, 131072);

    embed_kernel<<<(MM*EE + 255)/256, 256>>>(idx, tok, pos, x);
    pack_qkv_half<<<(LL*EE*E3 + 255)/256, 256>>>(Wq, Wk, Wv, wqkv);
    to_half_kernel<<<(LL*EE*EE + 255)/256, 256>>>(Wo, wo, LL*EE*EE);
    to_half_kernel<<<(LL*EE*FF + 255)/256, 256>>>(W1, w1, LL*EE*FF);
    to_half_kernel<<<(LL*FF*EE + 255)/256, 256>>>(W2, w2, LL*FF*EE);
    to_half_kernel<<<(EE*VVOC  + 255)/256, 256>>>(Wh, wh, EE*VVOC);

    dim3 blk(256);
    dim3 gQKV(E3/128, MM/128);
    dim3 gE(EE/128, MM/128);
    dim3 gF(FF/128, MM/128);
    dim3 gV(VVOC/128, MM/128);

    for (int l = 0; l < LL; l++) {
        ln_kernel<<<MM, 128>>>(x, h, ln1s + l*EE, ln1b + l*EE);
        hgemm_kernel<0><<<gQKV, blk, GEMM_SMEM>>>(h, wqkv + (size_t)l*EE*E3, nullptr, qkv, MM, E3, EE);
        attn_kernel<<<BV*HH, 512, 131072>>>(qkv, ao);
        hgemm_kernel<1><<<gE, blk, GEMM_SMEM>>>(ao, wo + (size_t)l*EE*EE, bo + l*EE, x, MM, EE, EE);
        ln_kernel<<<MM, 128>>>(x, h, ln2s + l*EE, ln2b + l*EE);
        hgemm_kernel<2><<<gF, blk, GEMM_SMEM>>>(h, w1 + (size_t)l*EE*FF, b1 + l*FF, ff, MM, FF, EE);
        hgemm_kernel<1><<<gE, blk, GEMM_SMEM>>>(ff, w2 + (size_t)l*FF*EE, b2 + l*EE, x, MM, EE, FF);
    }
    ln_kernel<<<MM, 128>>>(x, h, lnfs, lnfb);
    hgemm_kernel<0><<<gV, blk, GEMM_SMEM>>>(h, wh, bh, out, MM, VVOC, EE);
}

// round 9
// speedup vs baseline: 3.5393x; 1.0024x over previous
#include <cuda_runtime.h>
#include <cuda_fp16.h>
#include <math.h>
#include <stdint.h>

// Problem constants
#define BV 32
#define TT 256
#define EE 384
#define HH 6
#define DD 64
#define LL 6
#define FF 1536
#define VVOC 32000
#define MM (BV*TT)   // 8192
#define E3 (3*EE)    // 1152

// ---------------- scratch ----------------
__device__ float  g_x   [MM*EE];
__device__ float  g_qkv [MM*E3];
__device__ __half g_h   [MM*EE];
__device__ __half g_ao  [MM*EE];
__device__ __half g_ff  [(size_t)MM*FF];
__device__ __half g_wqkv[LL*EE*E3];
__device__ __half g_wo  [LL*EE*EE];
__device__ __half g_w1  [LL*EE*FF];
__device__ __half g_w2  [LL*FF*EE];
__device__ __half g_wh  [(size_t)EE*VVOC];

// ---------------- PTX helpers ----------------
__device__ __forceinline__ void cp_async16(uint32_t dst, const void* src) {
    asm volatile("cp.async.cg.shared.global [%0], [%1], 16;" :: "r"(dst), "l"(src));
}
__device__ __forceinline__ void cp_commit() { asm volatile("cp.async.commit_group;"); }
template<int N>
__device__ __forceinline__ void cp_wait() { asm volatile("cp.async.wait_group %0;" :: "n"(N)); }

__device__ __forceinline__ void ldsm_x4(uint32_t* r, uint32_t a) {
    asm volatile("ldmatrix.sync.aligned.m8n8.x4.shared.b16 {%0,%1,%2,%3}, [%4];"
        : "=r"(r[0]), "=r"(r[1]), "=r"(r[2]), "=r"(r[3]) : "r"(a));
}
__device__ __forceinline__ void ldsm_x4_t(uint32_t* r, uint32_t a) {
    asm volatile("ldmatrix.sync.aligned.m8n8.x4.trans.shared.b16 {%0,%1,%2,%3}, [%4];"
        : "=r"(r[0]), "=r"(r[1]), "=r"(r[2]), "=r"(r[3]) : "r"(a));
}
__device__ __forceinline__ void mma_f16(float* c, const uint32_t* a, const uint32_t* b) {
    asm volatile(
        "mma.sync.aligned.m16n8k16.row.col.f32.f16.f16.f32 "
        "{%0,%1,%2,%3}, {%4,%5,%6,%7}, {%8,%9}, {%0,%1,%2,%3};"
        : "+f"(c[0]), "+f"(c[1]), "+f"(c[2]), "+f"(c[3])
        : "r"(a[0]), "r"(a[1]), "r"(a[2]), "r"(a[3]), "r"(b[0]), "r"(b[1]));
}

// ---------------- embedding ----------------
__global__ void embed_kernel(const int* __restrict__ idx, const float* __restrict__ tok,
                             const float* __restrict__ pos, float* __restrict__ x)
{
    int i = blockIdx.x * blockDim.x + threadIdx.x;
    if (i >= MM*EE) return;
    int e   = i % EE;
    int row = i / EE;
    int t   = row % TT;
    x[i] = tok[(size_t)idx[row]*EE + e] + pos[t*EE + e];
}

// ---------------- weight prep ----------------
__global__ void to_half_kernel(const float* __restrict__ src, __half* __restrict__ dst, int n)
{
    int i = blockIdx.x * blockDim.x + threadIdx.x;
    if (i < n) dst[i] = __float2half_rn(src[i]);
}

__global__ void pack_qkv_half(const float* __restrict__ Wq, const float* __restrict__ Wk,
                              const float* __restrict__ Wv, __half* __restrict__ out)
{
    int i = blockIdx.x * blockDim.x + threadIdx.x;
    if (i >= LL*EE*E3) return;
    int c  = i % E3;
    int re = i / E3;
    int sel = c / EE;
    int cc  = c % EE;
    const float* src = (sel == 0) ? Wq : (sel == 1) ? Wk : Wv;
    out[i] = __float2half_rn(src[(size_t)re*EE + cc]);
}

// ---------------- layernorm -> fp16 (vectorized) ----------------
__global__ void ln_kernel(const float* __restrict__ in, __half* __restrict__ out,
                          const float* __restrict__ s, const float* __restrict__ b)
{
    int row = blockIdx.x;
    const float4* xr = (const float4*)(in + (size_t)row*EE);
    int tid = threadIdx.x;
    float4 v4 = make_float4(0.f,0.f,0.f,0.f);
    if (tid < 96) v4 = xr[tid];
    float ls = (v4.x + v4.y) + (v4.z + v4.w);
    float lq = (v4.x*v4.x + v4.y*v4.y) + (v4.z*v4.z + v4.w*v4.w);
    #pragma unroll
    for (int o = 16; o > 0; o >>= 1) {
        ls += __shfl_down_sync(0xffffffffu, ls, o);
        lq += __shfl_down_sync(0xffffffffu, lq, o);
    }
    __shared__ float ss[4], sq[4];
    int w = tid >> 5, lane = tid & 31;
    if (lane == 0) { ss[w] = ls; sq[w] = lq; }
    __syncthreads();
    float tot  = ss[0] + ss[1] + ss[2] + ss[3];
    float totq = sq[0] + sq[1] + sq[2] + sq[3];
    float mean = tot * (1.0f/EE);
    float var  = totq * (1.0f/EE) - mean*mean;
    float inv  = rsqrtf(var + 1e-5f);
    if (tid < 96) {
        const float4 s4 = ((const float4*)s)[tid];
        const float4 b4 = ((const float4*)b)[tid];
        float o0 = (v4.x - mean) * inv * s4.x + b4.x;
        float o1 = (v4.y - mean) * inv * s4.y + b4.y;
        float o2 = (v4.z - mean) * inv * s4.z + b4.z;
        float o3 = (v4.w - mean) * inv * s4.w + b4.w;
        __half2* op = (__half2*)(out + (size_t)row*EE + tid*4);
        op[0] = __floats2half2_rn(o0, o1);
        op[1] = __floats2half2_rn(o2, o3);
    }
}

// ---------------- fp16 tensor-core GEMM ----------------
// Block BM=128 x BN (128: 256thr/NST3/2CTA, 256: 512thr/NST4/1CTA), BK=64,
// warp tile 32x64, mma m16n8k16, cp.async multi-stage, single barrier/iter.
// MODE: 0 = f32 store, 1 = f32 accumulate into C, 2 = relu -> fp16 store
#define ATILE 16384          // 128 rows * 64 halves * 2B

template<int BN, int MODE>
__global__ void __launch_bounds__(BN == 256 ? 512 : 256, BN == 256 ? 1 : 2)
hgemm_kernel(const __half* __restrict__ A, const __half* __restrict__ B,
             const float* __restrict__ bias, void* __restrict__ Cv,
             int M, int N, int K)
{
    constexpr int T     = (BN == 256) ? 512 : 256;
    constexpr int NST   = (BN == 256) ? 4 : 3;
    constexpr int BTILE = 64 * BN * 2;
    constexpr int STAGE = ATILE + BTILE;
    constexpr int ITERA = 1024 / T;          // A: 1024 16B chunks
    constexpr int ITERB = (8 * BN) / T;      // B: 8*BN 16B chunks

    extern __shared__ char smem[];
    const uint32_t sb = (uint32_t)__cvta_generic_to_shared(smem);

    const int tid  = threadIdx.x;
    const int lane = tid & 31;
    const int wid  = tid >> 5;
    const int wm   = wid & 3;
    const int wn   = wid >> 2;
    const int g    = lane >> 2;
    const int t    = lane & 3;

    const int row0 = blockIdx.y * 128;
    const int col0 = blockIdx.x * BN;
    const int KT   = K >> 6;

    auto issue = [&](int kt) {
        uint32_t st = sb + (uint32_t)(kt % NST) * STAGE;
        #pragma unroll
        for (int i = 0; i < ITERA; i++) {
            int c = tid + T*i;
            int r = c >> 3, gg = c & 7;
            cp_async16(st + r*128 + 16*(gg ^ (r&7)),
                       A + (size_t)(row0 + r)*K + kt*64 + gg*8);
        }
        #pragma unroll
        for (int i = 0; i < ITERB; i++) {
            int c = tid + T*i;
            int k = c / (BN/8), gg = c % (BN/8);
            cp_async16(st + ATILE + k*(BN*2) + 16*(gg ^ (k&7)),
                       B + (size_t)(kt*64 + k)*N + col0 + gg*8);
        }
        cp_commit();
    };

    float acc[2][8][4];
    #pragma unroll
    for (int mi = 0; mi < 2; mi++)
        #pragma unroll
        for (int ni = 0; ni < 8; ni++)
            #pragma unroll
            for (int r = 0; r < 4; r++) acc[mi][ni][r] = 0.f;

    #pragma unroll
    for (int i = 0; i < NST-1; i++) issue(i);

    for (int kt = 0; kt < KT; kt++) {
        cp_wait<NST-2>();
        __syncthreads();
        if (kt + NST - 1 < KT) issue(kt + NST - 1);

        const uint32_t a_st = sb + (uint32_t)(kt % NST) * STAGE;
        const uint32_t b_st = a_st + ATILE;

        #pragma unroll
        for (int ks = 0; ks < 4; ks++) {
            uint32_t af[2][4], bf[8][2];
            #pragma unroll
            for (int mi = 0; mi < 2; mi++) {
                int m  = wm*32 + mi*16 + (lane & 15);
                int gg = ks*2 + (lane >> 4);
                ldsm_x4(af[mi], a_st + m*128 + 16*(gg ^ (m&7)));
            }
            #pragma unroll
            for (int np = 0; np < 4; np++) {
                int k  = ks*16 + (lane & 15);
                int gg = (wn*64 + np*16)/8 + (lane >> 4);
                uint32_t tmp[4];
                ldsm_x4_t(tmp, b_st + k*(BN*2) + 16*(gg ^ (k&7)));
                bf[np*2][0]   = tmp[0]; bf[np*2][1]   = tmp[1];
                bf[np*2+1][0] = tmp[2]; bf[np*2+1][1] = tmp[3];
            }
            #pragma unroll
            for (int mi = 0; mi < 2; mi++)
                #pragma unroll
                for (int ni = 0; ni < 8; ni++)
                    mma_f16(acc[mi][ni], af[mi], bf[ni]);
        }
    }

    __syncthreads();  // protect smem before potential reuse; also orders epilogue

    // epilogue
    #pragma unroll
    for (int mi = 0; mi < 2; mi++) {
        #pragma unroll
        for (int ni = 0; ni < 8; ni++) {
            int row = row0 + wm*32 + mi*16 + g;
            int col = col0 + wn*64 + ni*8 + t*2;
            float v0 = acc[mi][ni][0], v1 = acc[mi][ni][1];
            float v2 = acc[mi][ni][2], v3 = acc[mi][ni][3];
            if (bias) {
                float b0 = bias[col], b1 = bias[col+1];
                v0 += b0; v1 += b1; v2 += b0; v3 += b1;
            }
            if (MODE == 2) {
                v0 = fmaxf(v0, 0.f); v1 = fmaxf(v1, 0.f);
                v2 = fmaxf(v2, 0.f); v3 = fmaxf(v3, 0.f);
                __half* C = (__half*)Cv;
                *(__half2*)(C + (size_t)row * N + col)     = __floats2half2_rn(v0, v1);
                *(__half2*)(C + (size_t)(row+8) * N + col) = __floats2half2_rn(v2, v3);
            } else {
                float* C = (float*)Cv;
                float* c0 = C + (size_t)row * N + col;
                float* c1 = C + (size_t)(row + 8) * N + col;
                if (MODE == 1) {
                    float2 o0 = *(const float2*)c0;
                    float2 o1 = *(const float2*)c1;
                    v0 += o0.x; v1 += o0.y; v2 += o1.x; v3 += o1.y;
                }
                *(float2*)c0 = make_float2(v0, v1);
                *(float2*)c1 = make_float2(v2, v3);
            }
        }
    }
}

// ---------------- fused causal attention (fp32 in, fp16 out) ----------------
__global__ void __launch_bounds__(512)
attn_kernel(const float* __restrict__ qkv, __half* __restrict__ o)
{
    extern __shared__ float4 sm4[];
    float4* K4 = sm4;
    float4* V4 = sm4 + TT*16;

    int b = blockIdx.x / HH;
    int h = blockIdx.x % HH;
    int tid = threadIdx.x;

    const float* base = qkv + (size_t)b*TT*E3;
    for (int idx = tid; idx < TT*16; idx += 512) {
        int j  = idx >> 4;
        int d4 = idx & 15;
        K4[idx] = ((const float4*)(base + (size_t)j*E3 + EE   + h*DD))[d4];
        V4[idx] = ((const float4*)(base + (size_t)j*E3 + 2*EE + h*DD))[d4];
    }
    __syncthreads();

    int i = tid >> 1;
    int p = tid & 1;
    const float4* qg = (const float4*)(base + (size_t)i*E3 + h*DD);
    float4 qv[16];
    #pragma unroll
    for (int d4 = 0; d4 < 16; d4++) qv[d4] = qg[d4];

    float4 ov[16];
    #pragma unroll
    for (int d4 = 0; d4 < 16; d4++) ov[d4] = make_float4(0.f, 0.f, 0.f, 0.f);

    float m = -1e30f, lsum = 0.f;
    const float scale = 0.125f;

    for (int j = p; j <= i; j += 2) {
        float4 s4 = make_float4(0.f, 0.f, 0.f, 0.f);
        #pragma unroll
        for (int d4 = 0; d4 < 16; d4++) {
            float4 kk = K4[j*16 + d4];
            s4.x = fmaf(qv[d4].x, kk.x, s4.x);
            s4.y = fmaf(qv[d4].y, kk.y, s4.y);
            s4.z = fmaf(qv[d4].z, kk.z, s4.z);
            s4.w = fmaf(qv[d4].w, kk.w, s4.w);
        }
        float s = ((s4.x + s4.y) + (s4.z + s4.w)) * scale;
        float mn = fmaxf(m, s);
        float c = __expf(m - mn);
        float pw = __expf(s - mn);
        lsum = lsum * c + pw;
        #pragma unroll
        for (int d4 = 0; d4 < 16; d4++) {
            float4 vv = V4[j*16 + d4];
            ov[d4].x = fmaf(ov[d4].x, c, pw*vv.x);
            ov[d4].y = fmaf(ov[d4].y, c, pw*vv.y);
            ov[d4].z = fmaf(ov[d4].z, c, pw*vv.z);
            ov[d4].w = fmaf(ov[d4].w, c, pw*vv.w);
        }
        m = mn;
    }

    float mo = __shfl_xor_sync(0xffffffffu, m, 1);
    float lo = __shfl_xor_sync(0xffffffffu, lsum, 1);
    float mn = fmaxf(m, mo);
    float cs = __expf(m - mn);
    float co = __expf(mo - mn);
    float lm = lsum * cs + lo * co;
    float r = 1.0f / lm;

    __half* oh = o + (size_t)(b*TT + i)*EE + h*DD;
    #pragma unroll
    for (int d4 = 0; d4 < 16; d4++) {
        float ox = (ov[d4].x*cs + __shfl_xor_sync(0xffffffffu, ov[d4].x, 1)*co) * r;
        float oy = (ov[d4].y*cs + __shfl_xor_sync(0xffffffffu, ov[d4].y, 1)*co) * r;
        float oz = (ov[d4].z*cs + __shfl_xor_sync(0xffffffffu, ov[d4].z, 1)*co) * r;
        float ow = (ov[d4].w*cs + __shfl_xor_sync(0xffffffffu, ov[d4].w, 1)*co) * r;
        if (p == 0) {
            *(__half2*)(oh + d4*4)     = __floats2half2_rn(ox, oy);
            *(__half2*)(oh + d4*4 + 2) = __floats2half2_rn(oz, ow);
        }
    }
}

// ---------------- launcher ----------------
extern "C" void kernel_launch(void* const* d_in, const int* in_sizes, int n_in,
                              void* d_out, int out_size)
{
    (void)in_sizes; (void)n_in; (void)out_size;
    const int*   idx  = (const int*)  d_in[0];
    const float* tok  = (const float*)d_in[1];
    const float* pos  = (const float*)d_in[2];
    const float* Wq   = (const float*)d_in[3];
    const float* Wk   = (const float*)d_in[4];
    const float* Wv   = (const float*)d_in[5];
    const float* Wo   = (const float*)d_in[6];
    const float* bo   = (const float*)d_in[7];
    const float* ln1s = (const float*)d_in[8];
    const float* ln1b = (const float*)d_in[9];
    const float* ln2s = (const float*)d_in[10];
    const float* ln2b = (const float*)d_in[11];
    const float* W1   = (const float*)d_in[12];
    const float* b1   = (const float*)d_in[13];
    const float* W2   = (const float*)d_in[14];
    const float* b2   = (const float*)d_in[15];
    const float* lnfs = (const float*)d_in[16];
    const float* lnfb = (const float*)d_in[17];
    const float* Wh   = (const float*)d_in[18];
    const float* bh   = (const float*)d_in[19];
    float* out = (float*)d_out;

    float *x, *qkv;
    __half *h, *ao, *ff, *wqkv, *wo, *w1, *w2, *wh;
    cudaGetSymbolAddress((void**)&x,    g_x);
    cudaGetSymbolAddress((void**)&qkv,  g_qkv);
    cudaGetSymbolAddress((void**)&h,    g_h);
    cudaGetSymbolAddress((void**)&ao,   g_ao);
    cudaGetSymbolAddress((void**)&ff,   g_ff);
    cudaGetSymbolAddress((void**)&wqkv, g_wqkv);
    cudaGetSymbolAddress((void**)&wo,   g_wo);
    cudaGetSymbolAddress((void**)&w1,   g_w1);
    cudaGetSymbolAddress((void**)&w2,   g_w2);
    cudaGetSymbolAddress((void**)&wh,   g_wh);

    const int SM128 = 3*(ATILE + 64*128*2);   // 96 KB
    const int SM256 = 4*(ATILE + 64*256*2);   // 192 KB
    cudaFuncSetAttribute(hgemm_kernel<128,0>, cudaFuncAttributeMaxDynamicSharedMemorySize, SM128);
    cudaFuncSetAttribute(hgemm_kernel<128,1>, cudaFuncAttributeMaxDynamicSharedMemorySize, SM128);
    cudaFuncSetAttribute(hgemm_kernel<256,0>, cudaFuncAttributeMaxDynamicSharedMemorySize, SM256);
    cudaFuncSetAttribute(hgemm_kernel<256,2>, cudaFuncAttributeMaxDynamicSharedMemorySize, SM256);
    cudaFuncSetAttribute(attn_kernel, cudaFuncAttributeMaxDynamicSharedMemorySize, 131072);

    embed_kernel<<<(MM*EE + 255)/256, 256>>>(idx, tok, pos, x);
    pack_qkv_half<<<(LL*EE*E3 + 255)/256, 256>>>(Wq, Wk, Wv, wqkv);
    to_half_kernel<<<(LL*EE*EE + 255)/256, 256>>>(Wo, wo, LL*EE*EE);
    to_half_kernel<<<(LL*EE*FF + 255)/256, 256>>>(W1, w1, LL*EE*FF);
    to_half_kernel<<<(LL*FF*EE + 255)/256, 256>>>(W2, w2, LL*FF*EE);
    to_half_kernel<<<(EE*VVOC  + 255)/256, 256>>>(Wh, wh, EE*VVOC);

    dim3 gQKV(E3/128, MM/128);    // 9 x 64
    dim3 gE(EE/128, MM/128);      // 3 x 64
    dim3 gF(FF/256, MM/128);      // 6 x 64  (wide)
    dim3 gV(VVOC/256, MM/128);    // 125 x 64 (wide)

    for (int l = 0; l < LL; l++) {
        ln_kernel<<<MM, 128>>>(x, h, ln1s + l*EE, ln1b + l*EE);
        hgemm_kernel<128,0><<<gQKV, 256, SM128>>>(h, wqkv + (size_t)l*EE*E3, nullptr, qkv, MM, E3, EE);
        attn_kernel<<<BV*HH, 512, 131072>>>(qkv, ao);
        hgemm_kernel<128,1><<<gE, 256, SM128>>>(ao, wo + (size_t)l*EE*EE, bo + l*EE, x, MM, EE, EE);
        ln_kernel<<<MM, 128>>>(x, h, ln2s + l*EE, ln2b + l*EE);
        hgemm_kernel<256,2><<<gF, 512, SM256>>>(h, w1 + (size_t)l*EE*FF, b1 + l*FF, ff, MM, FF, EE);
        hgemm_kernel<128,1><<<gE, 256, SM128>>>(ff, w2 + (size_t)l*FF*EE, b2 + l*EE, x, MM, EE, FF);
    }
    ln_kernel<<<MM, 128>>>(x, h, lnfs, lnfb);
    hgemm_kernel<256,0><<<gV, 512, SM256>>>(h, wh, bh, out, MM, VVOC, EE);
}

// round 11
// speedup vs baseline: 6.6477x; 1.8782x over previous
#include <cuda_runtime.h>
#include <cuda_fp16.h>
#include <math.h>
#include <stdint.h>

// Problem constants
#define BV 32
#define TT 256
#define EE 384
#define HH 6
#define DD 64
#define LL 6
#define FF 1536
#define VVOC 32000
#define MM (BV*TT)   // 8192
#define E3 (3*EE)    // 1152

// ---------------- scratch ----------------
__device__ float  g_x   [MM*EE];
__device__ __half g_qkv [MM*E3];
__device__ __half g_h   [MM*EE];
__device__ __half g_ao  [MM*EE];
__device__ __half g_ff  [(size_t)MM*FF];
__device__ __half g_wqkv[LL*EE*E3];
__device__ __half g_wo  [LL*EE*EE];
__device__ __half g_w1  [LL*EE*FF];
__device__ __half g_w2  [LL*FF*EE];
__device__ __half g_wh  [(size_t)EE*VVOC];

// ---------------- PTX helpers ----------------
__device__ __forceinline__ void cp_async16(uint32_t dst, const void* src) {
    asm volatile("cp.async.cg.shared.global [%0], [%1], 16;" :: "r"(dst), "l"(src));
}
__device__ __forceinline__ void cp_commit() { asm volatile("cp.async.commit_group;"); }
template<int N>
__device__ __forceinline__ void cp_wait() { asm volatile("cp.async.wait_group %0;" :: "n"(N)); }

__device__ __forceinline__ void ldsm_x4(uint32_t* r, uint32_t a) {
    asm volatile("ldmatrix.sync.aligned.m8n8.x4.shared.b16 {%0,%1,%2,%3}, [%4];"
        : "=r"(r[0]), "=r"(r[1]), "=r"(r[2]), "=r"(r[3]) : "r"(a));
}
__device__ __forceinline__ void ldsm_x4_t(uint32_t* r, uint32_t a) {
    asm volatile("ldmatrix.sync.aligned.m8n8.x4.trans.shared.b16 {%0,%1,%2,%3}, [%4];"
        : "=r"(r[0]), "=r"(r[1]), "=r"(r[2]), "=r"(r[3]) : "r"(a));
}
__device__ __forceinline__ void mma_f16(float* c, const uint32_t* a, const uint32_t* b) {
    asm volatile(
        "mma.sync.aligned.m16n8k16.row.col.f32.f16.f16.f32 "
        "{%0,%1,%2,%3}, {%4,%5,%6,%7}, {%8,%9}, {%0,%1,%2,%3};"
        : "+f"(c[0]), "+f"(c[1]), "+f"(c[2]), "+f"(c[3])
        : "r"(a[0]), "r"(a[1]), "r"(a[2]), "r"(a[3]), "r"(b[0]), "r"(b[1]));
}

// ---------------- embedding ----------------
__global__ void embed_kernel(const int* __restrict__ idx, const float* __restrict__ tok,
                             const float* __restrict__ pos, float* __restrict__ x)
{
    int i = blockIdx.x * blockDim.x + threadIdx.x;
    if (i >= MM*EE) return;
    int e   = i % EE;
    int row = i / EE;
    int t   = row % TT;
    x[i] = tok[(size_t)idx[row]*EE + e] + pos[t*EE + e];
}

// ---------------- weight prep ----------------
__global__ void pack_qkv_half(const float* __restrict__ Wq, const float* __restrict__ Wk,
                              const float* __restrict__ Wv, __half* __restrict__ out)
{
    int i = blockIdx.x * blockDim.x + threadIdx.x;
    if (i >= LL*EE*E3) return;
    int c  = i % E3;
    int re = i / E3;
    int sel = c / EE;
    int cc  = c % EE;
    const float* src = (sel == 0) ? Wq : (sel == 1) ? Wk : Wv;
    out[i] = __float2half_rn(src[(size_t)re*EE + cc]);
}

__global__ void prep4_kernel(const float* __restrict__ Wo, const float* __restrict__ W1,
                             const float* __restrict__ W2, const float* __restrict__ Wh,
                             __half* __restrict__ wo, __half* __restrict__ w1,
                             __half* __restrict__ w2, __half* __restrict__ wh)
{
    const int N0 = LL*EE*EE, N1 = LL*EE*FF, N2 = LL*FF*EE;
    const int NH = EE*VVOC;
    int i = blockIdx.x * blockDim.x + threadIdx.x;
    if (i < N0)                 { wo[i] = __float2half_rn(Wo[i]); return; }
    i -= N0;
    if (i < N1)                 { w1[i] = __float2half_rn(W1[i]); return; }
    i -= N1;
    if (i < N2)                 { w2[i] = __float2half_rn(W2[i]); return; }
    i -= N2;
    if (i < NH)                 { wh[i] = __float2half_rn(Wh[i]); }
}

// ---------------- layernorm -> fp16 (vectorized) ----------------
__global__ void ln_kernel(const float* __restrict__ in, __half* __restrict__ out,
                          const float* __restrict__ s, const float* __restrict__ b)
{
    int row = blockIdx.x;
    const float4* xr = (const float4*)(in + (size_t)row*EE);
    int tid = threadIdx.x;
    float4 v4 = make_float4(0.f,0.f,0.f,0.f);
    if (tid < 96) v4 = xr[tid];
    float ls = (v4.x + v4.y) + (v4.z + v4.w);
    float lq = (v4.x*v4.x + v4.y*v4.y) + (v4.z*v4.z + v4.w*v4.w);
    #pragma unroll
    for (int o = 16; o > 0; o >>= 1) {
        ls += __shfl_down_sync(0xffffffffu, ls, o);
        lq += __shfl_down_sync(0xffffffffu, lq, o);
    }
    __shared__ float ss[4], sq[4];
    int w = tid >> 5, lane = tid & 31;
    if (lane == 0) { ss[w] = ls; sq[w] = lq; }
    __syncthreads();
    float tot  = ss[0] + ss[1] + ss[2] + ss[3];
    float totq = sq[0] + sq[1] + sq[2] + sq[3];
    float mean = tot * (1.0f/EE);
    float var  = totq * (1.0f/EE) - mean*mean;
    float inv  = rsqrtf(var + 1e-5f);
    if (tid < 96) {
        const float4 s4 = ((const float4*)s)[tid];
        const float4 b4 = ((const float4*)b)[tid];
        float o0 = (v4.x - mean) * inv * s4.x + b4.x;
        float o1 = (v4.y - mean) * inv * s4.y + b4.y;
        float o2 = (v4.z - mean) * inv * s4.z + b4.z;
        float o3 = (v4.w - mean) * inv * s4.w + b4.w;
        __half2* op = (__half2*)(out + (size_t)row*EE + tid*4);
        op[0] = __floats2half2_rn(o0, o1);
        op[1] = __floats2half2_rn(o2, o3);
    }
}

// ---------------- fp16 tensor-core GEMM ----------------
// MODE: 0 = f32 store, 1 = f32 accumulate into C, 2 = relu -> fp16 store, 3 = fp16 store
#define ATILE 16384          // 128 rows * 64 halves * 2B

template<int BN, int MODE>
__global__ void __launch_bounds__(BN == 256 ? 512 : 256, BN == 256 ? 1 : 2)
hgemm_kernel(const __half* __restrict__ A, const __half* __restrict__ B,
             const float* __restrict__ bias, void* __restrict__ Cv,
             int M, int N, int K)
{
    constexpr int T     = (BN == 256) ? 512 : 256;
    constexpr int NST   = (BN == 256) ? 4 : 3;
    constexpr int BTILE = 64 * BN * 2;
    constexpr int STAGE = ATILE + BTILE;
    constexpr int ITERA = 1024 / T;
    constexpr int ITERB = (8 * BN) / T;

    extern __shared__ char smem[];
    const uint32_t sb = (uint32_t)__cvta_generic_to_shared(smem);

    const int tid  = threadIdx.x;
    const int lane = tid & 31;
    const int wid  = tid >> 5;
    const int wm   = wid & 3;
    const int wn   = wid >> 2;
    const int g    = lane >> 2;
    const int t    = lane & 3;

    const int row0 = blockIdx.y * 128;
    const int col0 = blockIdx.x * BN;
    const int KT   = K >> 6;

    auto issue = [&](int kt) {
        uint32_t st = sb + (uint32_t)(kt % NST) * STAGE;
        #pragma unroll
        for (int i = 0; i < ITERA; i++) {
            int c = tid + T*i;
            int r = c >> 3, gg = c & 7;
            cp_async16(st + r*128 + 16*(gg ^ (r&7)),
                       A + (size_t)(row0 + r)*K + kt*64 + gg*8);
        }
        #pragma unroll
        for (int i = 0; i < ITERB; i++) {
            int c = tid + T*i;
            int k = c / (BN/8), gg = c % (BN/8);
            cp_async16(st + ATILE + k*(BN*2) + 16*(gg ^ (k&7)),
                       B + (size_t)(kt*64 + k)*N + col0 + gg*8);
        }
        cp_commit();
    };

    float acc[2][8][4];
    #pragma unroll
    for (int mi = 0; mi < 2; mi++)
        #pragma unroll
        for (int ni = 0; ni < 8; ni++)
            #pragma unroll
            for (int r = 0; r < 4; r++) acc[mi][ni][r] = 0.f;

    #pragma unroll
    for (int i = 0; i < NST-1; i++) issue(i);

    for (int kt = 0; kt < KT; kt++) {
        cp_wait<NST-2>();
        __syncthreads();
        if (kt + NST - 1 < KT) issue(kt + NST - 1);

        const uint32_t a_st = sb + (uint32_t)(kt % NST) * STAGE;
        const uint32_t b_st = a_st + ATILE;

        #pragma unroll
        for (int ks = 0; ks < 4; ks++) {
            uint32_t af[2][4], bf[8][2];
            #pragma unroll
            for (int mi = 0; mi < 2; mi++) {
                int m  = wm*32 + mi*16 + (lane & 15);
                int gg = ks*2 + (lane >> 4);
                ldsm_x4(af[mi], a_st + m*128 + 16*(gg ^ (m&7)));
            }
            #pragma unroll
            for (int np = 0; np < 4; np++) {
                int k  = ks*16 + (lane & 15);
                int gg = (wn*64 + np*16)/8 + (lane >> 4);
                uint32_t tmp[4];
                ldsm_x4_t(tmp, b_st + k*(BN*2) + 16*(gg ^ (k&7)));
                bf[np*2][0]   = tmp[0]; bf[np*2][1]   = tmp[1];
                bf[np*2+1][0] = tmp[2]; bf[np*2+1][1] = tmp[3];
            }
            #pragma unroll
            for (int mi = 0; mi < 2; mi++)
                #pragma unroll
                for (int ni = 0; ni < 8; ni++)
                    mma_f16(acc[mi][ni], af[mi], bf[ni]);
        }
    }

    __syncthreads();

    #pragma unroll
    for (int mi = 0; mi < 2; mi++) {
        #pragma unroll
        for (int ni = 0; ni < 8; ni++) {
            int row = row0 + wm*32 + mi*16 + g;
            int col = col0 + wn*64 + ni*8 + t*2;
            float v0 = acc[mi][ni][0], v1 = acc[mi][ni][1];
            float v2 = acc[mi][ni][2], v3 = acc[mi][ni][3];
            if (bias) {
                float b0 = bias[col], b1 = bias[col+1];
                v0 += b0; v1 += b1; v2 += b0; v3 += b1;
            }
            if (MODE == 2 || MODE == 3) {
                if (MODE == 2) {
                    v0 = fmaxf(v0, 0.f); v1 = fmaxf(v1, 0.f);
                    v2 = fmaxf(v2, 0.f); v3 = fmaxf(v3, 0.f);
                }
                __half* C = (__half*)Cv;
                *(__half2*)(C + (size_t)row * N + col)     = __floats2half2_rn(v0, v1);
                *(__half2*)(C + (size_t)(row+8) * N + col) = __floats2half2_rn(v2, v3);
            } else {
                float* C = (float*)Cv;
                float* c0 = C + (size_t)row * N + col;
                float* c1 = C + (size_t)(row + 8) * N + col;
                if (MODE == 1) {
                    float2 o0 = *(const float2*)c0;
                    float2 o1 = *(const float2*)c1;
                    v0 += o0.x; v1 += o0.y; v2 += o1.x; v3 += o1.y;
                }
                *(float2*)c0 = make_float2(v0, v1);
                *(float2*)c1 = make_float2(v2, v3);
            }
        }
    }
}

// ---------------- flash attention (tensor-core), one (b,h) per block ----------------
#define FA_SMEM 98304

__global__ void __launch_bounds__(256)
fattn_kernel(const __half* __restrict__ qkv, __half* __restrict__ o)
{
    extern __shared__ char sm[];
    const uint32_t sb = (uint32_t)__cvta_generic_to_shared(sm);
    const uint32_t Qs = sb, Ks = sb + 32768, Vs = sb + 65536;

    const int b = blockIdx.x / HH;
    const int h = blockIdx.x % HH;
    const int tid  = threadIdx.x;
    const int lane = tid & 31;
    const int w    = tid >> 5;
    const int g    = lane >> 2;
    const int t    = lane & 3;

    // ---- load Q,K,V fp16 into swizzled smem ----
    const __half* base = qkv + (size_t)b*TT*E3 + h*DD;
    #pragma unroll
    for (int i = 0; i < 24; i++) {
        int idx = tid + 256*i;
        int sec = idx >> 11;
        int rem = idx & 2047;
        int seq = rem >> 3, c8 = rem & 7;
        uint32_t dst = sb + sec*32768 + seq*128 + 16*(c8 ^ (seq & 7));
        cp_async16(dst, base + (size_t)seq*E3 + sec*EE + c8*8);
    }
    cp_commit();
    cp_wait<0>();
    __syncthreads();

    // ---- Q fragments ----
    uint32_t qf[2][4][4];
    #pragma unroll
    for (int mi = 0; mi < 2; mi++)
        #pragma unroll
        for (int kk = 0; kk < 4; kk++) {
            int r  = w*32 + mi*16 + (lane & 15);
            int gg = kk*2 + (lane >> 4);
            ldsm_x4(qf[mi][kk], Qs + r*128 + 16*(gg ^ (r & 7)));
        }

    float acc_o[2][8][4];
    #pragma unroll
    for (int mi = 0; mi < 2; mi++)
        #pragma unroll
        for (int ni = 0; ni < 8; ni++)
            #pragma unroll
            for (int c = 0; c < 4; c++) acc_o[mi][ni][c] = 0.f;
    float acc_l[2][4] = {{0.f,0.f,0.f,0.f},{0.f,0.f,0.f,0.f}};
    float mrow[2][2] = {{-1e30f,-1e30f},{-1e30f,-1e30f}};

    const float kscale = 0.125f * 1.44269504f;   // scale * log2(e)
    uint32_t onesf[2];
    onesf[0] = (g == 0) ? 0x3C003C00u : 0u;
    onesf[1] = onesf[0];

    const int nchunks = (w >> 1) + 1;
    for (int c = 0; c < nchunks; c++) {
        // ---- S = Q K^T ----
        float s[2][8][4];
        #pragma unroll
        for (int mi = 0; mi < 2; mi++)
            #pragma unroll
            for (int ni = 0; ni < 8; ni++)
                #pragma unroll
                for (int cc = 0; cc < 4; cc++) s[mi][ni][cc] = 0.f;

        #pragma unroll
        for (int kk = 0; kk < 4; kk++) {
            uint32_t kf[8][2];
            #pragma unroll
            for (int nb = 0; nb < 4; nb++) {
                int r  = c*64 + nb*16 + (lane & 15);
                int gg = kk*2 + (lane >> 4);
                uint32_t tmp[4];
                ldsm_x4(tmp, Ks + r*128 + 16*(gg ^ (r & 7)));
                kf[nb*2][0]   = tmp[0]; kf[nb*2][1]   = tmp[2];
                kf[nb*2+1][0] = tmp[1]; kf[nb*2+1][1] = tmp[3];
            }
            #pragma unroll
            for (int mi = 0; mi < 2; mi++)
                #pragma unroll
                for (int ni = 0; ni < 8; ni++)
                    mma_f16(s[mi][ni], qf[mi][kk], kf[ni]);
        }

        // ---- causal mask on diagonal chunk ----
        if (c == (w >> 1)) {
            #pragma unroll
            for (int mi = 0; mi < 2; mi++) {
                int r0 = w*32 + mi*16 + g;
                #pragma unroll
                for (int ni = 0; ni < 8; ni++) {
                    int col = c*64 + ni*8 + t*2;
                    if (col     > r0)     s[mi][ni][0] = -1e30f;
                    if (col + 1 > r0)     s[mi][ni][1] = -1e30f;
                    if (col     > r0 + 8) s[mi][ni][2] = -1e30f;
                    if (col + 1 > r0 + 8) s[mi][ni][3] = -1e30f;
                }
            }
        }

        // ---- softmax state update ----
        float mk[2][2];
        #pragma unroll
        for (int mi = 0; mi < 2; mi++) {
            float mx0 = -1e30f, mx1 = -1e30f;
            #pragma unroll
            for (int ni = 0; ni < 8; ni++) {
                mx0 = fmaxf(mx0, fmaxf(s[mi][ni][0], s[mi][ni][1]));
                mx1 = fmaxf(mx1, fmaxf(s[mi][ni][2], s[mi][ni][3]));
            }
            mx0 = fmaxf(mx0, __shfl_xor_sync(0xffffffffu, mx0, 1));
            mx0 = fmaxf(mx0, __shfl_xor_sync(0xffffffffu, mx0, 2));
            mx1 = fmaxf(mx1, __shfl_xor_sync(0xffffffffu, mx1, 1));
            mx1 = fmaxf(mx1, __shfl_xor_sync(0xffffffffu, mx1, 2));
            float mn0 = fmaxf(mrow[mi][0], mx0);
            float mn1 = fmaxf(mrow[mi][1], mx1);
            float c0 = exp2f((mrow[mi][0] - mn0) * kscale);
            float c1 = exp2f((mrow[mi][1] - mn1) * kscale);
            mrow[mi][0] = mn0; mrow[mi][1] = mn1;
            mk[mi][0] = mn0 * kscale;
            mk[mi][1] = mn1 * kscale;
            #pragma unroll
            for (int ni = 0; ni < 8; ni++) {
                acc_o[mi][ni][0] *= c0; acc_o[mi][ni][1] *= c0;
                acc_o[mi][ni][2] *= c1; acc_o[mi][ni][3] *= c1;
            }
            acc_l[mi][0] *= c0; acc_l[mi][1] *= c0;
            acc_l[mi][2] *= c1; acc_l[mi][3] *= c1;
        }

        // ---- P = exp2(S*kscale - m*kscale) in A-frag layout; O += P V; l += P 1 ----
        #pragma unroll
        for (int kk2 = 0; kk2 < 4; kk2++) {
            uint32_t pa[2][4];
            #pragma unroll
            for (int mi = 0; mi < 2; mi++) {
                #pragma unroll
                for (int q = 0; q < 2; q++) {
                    int ni = kk2*2 + q;
                    float e0 = exp2f(s[mi][ni][0]*kscale - mk[mi][0]);
                    float e1 = exp2f(s[mi][ni][1]*kscale - mk[mi][0]);
                    float e2 = exp2f(s[mi][ni][2]*kscale - mk[mi][1]);
                    float e3 = exp2f(s[mi][ni][3]*kscale - mk[mi][1]);
                    __half2 h01 = __floats2half2_rn(e0, e1);   // row g
                    __half2 h23 = __floats2half2_rn(e2, e3);   // row g+8
                    pa[mi][q*2 + 0] = *(uint32_t*)&h01;        // a0 / a2
                    pa[mi][q*2 + 1] = *(uint32_t*)&h23;        // a1 / a3
                }
            }
            uint32_t vf[8][2];
            #pragma unroll
            for (int nb = 0; nb < 4; nb++) {
                int k  = c*64 + kk2*16 + (lane & 15);
                int gg = nb*2 + (lane >> 4);
                uint32_t tmp[4];
                ldsm_x4_t(tmp, Vs + k*128 + 16*(gg ^ (k & 7)));
                vf[nb*2][0]   = tmp[0]; vf[nb*2][1]   = tmp[1];
                vf[nb*2+1][0] = tmp[2]; vf[nb*2+1][1] = tmp[3];
            }
            #pragma unroll
            for (int mi = 0; mi < 2; mi++) {
                mma_f16(acc_l[mi], pa[mi], onesf);
                #pragma unroll
                for (int dn = 0; dn < 8; dn++)
                    mma_f16(acc_o[mi][dn], pa[mi], vf[dn]);
            }
        }
    }

    // ---- finalize: divide by l, write fp16 ----
    #pragma unroll
    for (int mi = 0; mi < 2; mi++) {
        float l0 = __shfl_sync(0xffffffffu, acc_l[mi][0], lane & ~3);
        float l1 = __shfl_sync(0xffffffffu, acc_l[mi][2], lane & ~3);
        float r0 = 1.0f / l0;
        float r1 = 1.0f / l1;
        int row = w*32 + mi*16 + g;
        __half* op0 = o + (size_t)(b*TT + row)     * EE + h*DD;
        __half* op1 = o + (size_t)(b*TT + row + 8) * EE + h*DD;
        #pragma unroll
        for (int ni = 0; ni < 8; ni++) {
            *(__half2*)(op0 + ni*8 + t*2) =
                __floats2half2_rn(acc_o[mi][ni][0]*r0, acc_o[mi][ni][1]*r0);
            *(__half2*)(op1 + ni*8 + t*2) =
                __floats2half2_rn(acc_o[mi][ni][2]*r1, acc_o[mi][ni][3]*r1);
        }
    }
}

// ---------------- launcher ----------------
extern "C" void kernel_launch(void* const* d_in, const int* in_sizes, int n_in,
                              void* d_out, int out_size)
{
    (void)in_sizes; (void)n_in; (void)out_size;
    const int*   idx  = (const int*)  d_in[0];
    const float* tok  = (const float*)d_in[1];
    const float* pos  = (const float*)d_in[2];
    const float* Wq   = (const float*)d_in[3];
    const float* Wk   = (const float*)d_in[4];
    const float* Wv   = (const float*)d_in[5];
    const float* Wo   = (const float*)d_in[6];
    const float* bo   = (const float*)d_in[7];
    const float* ln1s = (const float*)d_in[8];
    const float* ln1b = (const float*)d_in[9];
    const float* ln2s = (const float*)d_in[10];
    const float* ln2b = (const float*)d_in[11];
    const float* W1   = (const float*)d_in[12];
    const float* b1   = (const float*)d_in[13];
    const float* W2   = (const float*)d_in[14];
    const float* b2   = (const float*)d_in[15];
    const float* lnfs = (const float*)d_in[16];
    const float* lnfb = (const float*)d_in[17];
    const float* Wh   = (const float*)d_in[18];
    const float* bh   = (const float*)d_in[19];
    float* out = (float*)d_out;

    float *x;
    __half *qkv, *h, *ao, *ff, *wqkv, *wo, *w1, *w2, *wh;
    cudaGetSymbolAddress((void**)&x,    g_x);
    cudaGetSymbolAddress((void**)&qkv,  g_qkv);
    cudaGetSymbolAddress((void**)&h,    g_h);
    cudaGetSymbolAddress((void**)&ao,   g_ao);
    cudaGetSymbolAddress((void**)&ff,   g_ff);
    cudaGetSymbolAddress((void**)&wqkv, g_wqkv);
    cudaGetSymbolAddress((void**)&wo,   g_wo);
    cudaGetSymbolAddress((void**)&w1,   g_w1);
    cudaGetSymbolAddress((void**)&w2,   g_w2);
    cudaGetSymbolAddress((void**)&wh,   g_wh);

    const int SM128 = 3*(ATILE + 64*128*2);   // 96 KB
    const int SM256 = 4*(ATILE + 64*256*2);   // 192 KB
    cudaFuncSetAttribute(hgemm_kernel<128,1>, cudaFuncAttributeMaxDynamicSharedMemorySize, SM128);
    cudaFuncSetAttribute(hgemm_kernel<128,3>, cudaFuncAttributeMaxDynamicSharedMemorySize, SM128);
    cudaFuncSetAttribute(hgemm_kernel<256,0>, cudaFuncAttributeMaxDynamicSharedMemorySize, SM256);
    cudaFuncSetAttribute(hgemm_kernel<256,2>, cudaFuncAttributeMaxDynamicSharedMemorySize, SM256);
    cudaFuncSetAttribute(fattn_kernel, cudaFuncAttributeMaxDynamicSharedMemorySize, FA_SMEM);

    embed_kernel<<<(MM*EE + 255)/256, 256>>>(idx, tok, pos, x);
    pack_qkv_half<<<(LL*EE*E3 + 255)/256, 256>>>(Wq, Wk, Wv, wqkv);
    {
        int ntot = LL*EE*EE + LL*EE*FF + LL*FF*EE + EE*VVOC;
        prep4_kernel<<<(ntot + 255)/256, 256>>>(Wo, W1, W2, Wh, wo, w1, w2, wh);
    }

    dim3 gQKV(E3/128, MM/128);
    dim3 gE(EE/128, MM/128);
    dim3 gF(FF/256, MM/128);
    dim3 gV(VVOC/256, MM/128);

    for (int l = 0; l < LL; l++) {
        ln_kernel<<<MM, 128>>>(x, h, ln1s + l*EE, ln1b + l*EE);
        hgemm_kernel<128,3><<<gQKV, 256, SM128>>>(h, wqkv + (size_t)l*EE*E3, nullptr, qkv, MM, E3, EE);
        fattn_kernel<<<BV*HH, 256, FA_SMEM>>>(qkv, ao);
        hgemm_kernel<128,1><<<gE, 256, SM128>>>(ao, wo + (size_t)l*EE*EE, bo + l*EE, x, MM, EE, EE);
        ln_kernel<<<MM, 128>>>(x, h, ln2s + l*EE, ln2b + l*EE);
        hgemm_kernel<256,2><<<gF, 512, SM256>>>(h, w1 + (size_t)l*EE*FF, b1 + l*FF, ff, MM, FF, EE);
        hgemm_kernel<128,1><<<gE, 256, SM128>>>(ff, w2 + (size_t)l*FF*EE, b2 + l*EE, x, MM, EE, FF);
    }
    ln_kernel<<<MM, 128>>>(x, h, lnfs, lnfb);
    hgemm_kernel<256,0><<<gV, 512, SM256>>>(h, wh, bh, out, MM, VVOC, EE);
}